// round 11
// baseline (speedup 1.0000x reference)
#include <cuda_runtime.h>
#include <cstddef>

#define N_NODES 100000
#define N_EDGES 3200000
#define D_IN    128
#define D_HID   128
#define D_OUT   64
#define NBLK    391           // ceil(N_NODES / 256)

// ---------------- scratch (no allocation allowed) ----------------
__device__ __align__(16) float g_agg1[(size_t)N_NODES * D_IN];   // mean-agg of x
__device__ __align__(16) float g_t   [(size_t)N_NODES * D_OUT];  // h @ W_l2^T
__device__ __align__(16) float g_r   [(size_t)N_NODES * D_OUT];  // h @ W_r2^T + b2
__device__ __align__(16) float g_h   [(size_t)N_NODES * D_HID];  // fallback h storage
__device__ int  g_deg [N_NODES];
__device__ int  g_off [N_NODES + 1];
__device__ int  g_pos [N_NODES];
__device__ int  g_bsum[NBLK];
__device__ __align__(16) int2 g_edge[N_EDGES];                   // (src, w-bits), dst-grouped
__device__ int  g_idx64;   // 1 if edge_index is int64, 0 if int32

// ---------------- f32x2 helpers ----------------
__device__ __forceinline__ unsigned long long ffma2(unsigned long long a,
                                                    unsigned long long b,
                                                    unsigned long long c) {
    unsigned long long d;
    asm("fma.rn.f32x2 %0, %1, %2, %3;" : "=l"(d) : "l"(a), "l"(b), "l"(c));
    return d;
}
__device__ __forceinline__ void unpack2(unsigned long long d, float& lo, float& hi) {
    asm("mov.b64 {%0, %1}, %2;" : "=f"(lo), "=f"(hi) : "l"(d));
}

// Load edge endpoint #e (src if half==0, dst if half==1) honoring detected dtype.
__device__ __forceinline__ int load_idx(const void* ei, int e, int half, int mode64) {
    if (mode64) {
        long long v = __ldg(reinterpret_cast<const long long*>(ei) +
                            (size_t)half * N_EDGES + e);
        return (int)v;
    } else {
        return __ldg(reinterpret_cast<const int*>(ei) + (size_t)half * N_EDGES + e);
    }
}

// ---------------- dtype detection + zero deg (merged) ----------------
__global__ void detect_zero_kernel(const int* __restrict__ ei_words) {
    int i = blockIdx.x * 256 + threadIdx.x;
    if (i < N_NODES) g_deg[i] = 0;
    if (blockIdx.x == 0) {
        __shared__ int any_nonzero;
        if (threadIdx.x == 0) any_nonzero = 0;
        __syncthreads();
        int acc = 0;
        for (int k = threadIdx.x; k < 4096; k += 256)
            acc |= ei_words[2 * k + 1];
        if (acc) atomicOr(&any_nonzero, 1);
        __syncthreads();
        if (threadIdx.x == 0) g_idx64 = any_nonzero ? 0 : 1;
    }
}

// ---------------- CSR build ----------------
__global__ void hist_kernel(const void* __restrict__ ei) {
    int e = blockIdx.x * blockDim.x + threadIdx.x;
    if (e >= N_EDGES) return;
    int mode64 = g_idx64;
    int d = load_idx(ei, e, 1, mode64);
    if ((unsigned)d < N_NODES) atomicAdd(&g_deg[d], 1);
}

__global__ void blocksum_kernel() {
    __shared__ int s[256];
    int i = blockIdx.x * 256 + threadIdx.x;
    s[threadIdx.x] = (i < N_NODES) ? g_deg[i] : 0;
    __syncthreads();
    for (int d = 128; d > 0; d >>= 1) {
        if (threadIdx.x < d) s[threadIdx.x] += s[threadIdx.x + d];
        __syncthreads();
    }
    if (threadIdx.x == 0) g_bsum[blockIdx.x] = s[0];
}

// merged: every block scans all NBLK block-sums in smem (391 ints), then
// scans its own 256 degrees. 512 threads.
__global__ void offsets_kernel() {
    __shared__ int bs[512];
    __shared__ int s[512];
    int t = threadIdx.x;
    int bv = (t < NBLK) ? g_bsum[t] : 0;
    bs[t] = bv;
    __syncthreads();
    for (int d = 1; d < 512; d <<= 1) {
        int tmp = (t >= d) ? bs[t - d] : 0;
        __syncthreads();
        bs[t] += tmp;
        __syncthreads();
    }
    int bpre = (blockIdx.x == 0) ? 0 : bs[blockIdx.x - 1];
    if (blockIdx.x == 0 && t == 0) g_off[N_NODES] = bs[NBLK - 1];
    int i = blockIdx.x * 256 + t;
    int v = (t < 256 && i < N_NODES) ? g_deg[i] : 0;
    s[t] = v;
    __syncthreads();
    for (int d = 1; d < 512; d <<= 1) {
        int tmp = (t >= d) ? s[t - d] : 0;
        __syncthreads();
        s[t] += tmp;
        __syncthreads();
    }
    if (t < 256 && i < N_NODES) {
        int off = bpre + s[t] - v;
        g_off[i] = off;
        g_pos[i] = off;
    }
}

__global__ void fill_kernel(const void* __restrict__ ei,
                            const float* __restrict__ ew) {
    int e = blockIdx.x * blockDim.x + threadIdx.x;
    if (e >= N_EDGES) return;
    int mode64 = g_idx64;
    int s = load_idx(ei, e, 0, mode64);
    int d = load_idx(ei, e, 1, mode64);
    if ((unsigned)s >= N_NODES || (unsigned)d >= N_NODES) return;
    int p = atomicAdd(&g_pos[d], 1);
    g_edge[p] = make_int2(s, __float_as_int(__ldg(&ew[e])));
}

// ---------------- gather1: agg1[n] = mean over in-edges of x[src]*w ----------------
// one warp per node; lane covers 4 features (float4); batches of 8 with
// cross-batch edge prefetch: MLP ~= 16 (8 feature loads + 8 edge prefetch)
__global__ void gather1_kernel(const float* __restrict__ x) {
    int n = (blockIdx.x * blockDim.x + threadIdx.x) >> 5;
    if (n >= N_NODES) return;
    int lane = threadIdx.x & 31;
    int off = g_off[n], end = g_off[n + 1];
    float4 a0 = make_float4(0.f, 0.f, 0.f, 0.f);
    float4 a1 = a0, a2 = a0, a3 = a0, a4 = a0, a5 = a0, a6 = a0, a7 = a0;
    int i = off;
    int2 e0, e1, e2, e3, e4, e5, e6, e7;
    bool have = (i + 8 <= end);
    if (have) {
        e0 = __ldg(reinterpret_cast<const int2*>(g_edge) + i + 0);
        e1 = __ldg(reinterpret_cast<const int2*>(g_edge) + i + 1);
        e2 = __ldg(reinterpret_cast<const int2*>(g_edge) + i + 2);
        e3 = __ldg(reinterpret_cast<const int2*>(g_edge) + i + 3);
        e4 = __ldg(reinterpret_cast<const int2*>(g_edge) + i + 4);
        e5 = __ldg(reinterpret_cast<const int2*>(g_edge) + i + 5);
        e6 = __ldg(reinterpret_cast<const int2*>(g_edge) + i + 6);
        e7 = __ldg(reinterpret_cast<const int2*>(g_edge) + i + 7);
    }
    for (; i + 16 <= end; i += 8) {
        int2 f0 = __ldg(reinterpret_cast<const int2*>(g_edge) + i + 8);
        int2 f1 = __ldg(reinterpret_cast<const int2*>(g_edge) + i + 9);
        int2 f2 = __ldg(reinterpret_cast<const int2*>(g_edge) + i + 10);
        int2 f3 = __ldg(reinterpret_cast<const int2*>(g_edge) + i + 11);
        int2 f4 = __ldg(reinterpret_cast<const int2*>(g_edge) + i + 12);
        int2 f5 = __ldg(reinterpret_cast<const int2*>(g_edge) + i + 13);
        int2 f6 = __ldg(reinterpret_cast<const int2*>(g_edge) + i + 14);
        int2 f7 = __ldg(reinterpret_cast<const int2*>(g_edge) + i + 15);
        float4 v0 = __ldg(reinterpret_cast<const float4*>(x + (size_t)e0.x * D_IN) + lane);
        float4 v1 = __ldg(reinterpret_cast<const float4*>(x + (size_t)e1.x * D_IN) + lane);
        float4 v2 = __ldg(reinterpret_cast<const float4*>(x + (size_t)e2.x * D_IN) + lane);
        float4 v3 = __ldg(reinterpret_cast<const float4*>(x + (size_t)e3.x * D_IN) + lane);
        float4 v4 = __ldg(reinterpret_cast<const float4*>(x + (size_t)e4.x * D_IN) + lane);
        float4 v5 = __ldg(reinterpret_cast<const float4*>(x + (size_t)e5.x * D_IN) + lane);
        float4 v6 = __ldg(reinterpret_cast<const float4*>(x + (size_t)e6.x * D_IN) + lane);
        float4 v7 = __ldg(reinterpret_cast<const float4*>(x + (size_t)e7.x * D_IN) + lane);
        float w0 = __int_as_float(e0.y), w1 = __int_as_float(e1.y);
        float w2 = __int_as_float(e2.y), w3 = __int_as_float(e3.y);
        float w4 = __int_as_float(e4.y), w5 = __int_as_float(e5.y);
        float w6 = __int_as_float(e6.y), w7 = __int_as_float(e7.y);
        a0.x = fmaf(v0.x, w0, a0.x); a0.y = fmaf(v0.y, w0, a0.y);
        a0.z = fmaf(v0.z, w0, a0.z); a0.w = fmaf(v0.w, w0, a0.w);
        a1.x = fmaf(v1.x, w1, a1.x); a1.y = fmaf(v1.y, w1, a1.y);
        a1.z = fmaf(v1.z, w1, a1.z); a1.w = fmaf(v1.w, w1, a1.w);
        a2.x = fmaf(v2.x, w2, a2.x); a2.y = fmaf(v2.y, w2, a2.y);
        a2.z = fmaf(v2.z, w2, a2.z); a2.w = fmaf(v2.w, w2, a2.w);
        a3.x = fmaf(v3.x, w3, a3.x); a3.y = fmaf(v3.y, w3, a3.y);
        a3.z = fmaf(v3.z, w3, a3.z); a3.w = fmaf(v3.w, w3, a3.w);
        a4.x = fmaf(v4.x, w4, a4.x); a4.y = fmaf(v4.y, w4, a4.y);
        a4.z = fmaf(v4.z, w4, a4.z); a4.w = fmaf(v4.w, w4, a4.w);
        a5.x = fmaf(v5.x, w5, a5.x); a5.y = fmaf(v5.y, w5, a5.y);
        a5.z = fmaf(v5.z, w5, a5.z); a5.w = fmaf(v5.w, w5, a5.w);
        a6.x = fmaf(v6.x, w6, a6.x); a6.y = fmaf(v6.y, w6, a6.y);
        a6.z = fmaf(v6.z, w6, a6.z); a6.w = fmaf(v6.w, w6, a6.w);
        a7.x = fmaf(v7.x, w7, a7.x); a7.y = fmaf(v7.y, w7, a7.y);
        a7.z = fmaf(v7.z, w7, a7.z); a7.w = fmaf(v7.w, w7, a7.w);
        e0 = f0; e1 = f1; e2 = f2; e3 = f3;
        e4 = f4; e5 = f5; e6 = f6; e7 = f7;
    }
    if (have) {
        float4 v0 = __ldg(reinterpret_cast<const float4*>(x + (size_t)e0.x * D_IN) + lane);
        float4 v1 = __ldg(reinterpret_cast<const float4*>(x + (size_t)e1.x * D_IN) + lane);
        float4 v2 = __ldg(reinterpret_cast<const float4*>(x + (size_t)e2.x * D_IN) + lane);
        float4 v3 = __ldg(reinterpret_cast<const float4*>(x + (size_t)e3.x * D_IN) + lane);
        float4 v4 = __ldg(reinterpret_cast<const float4*>(x + (size_t)e4.x * D_IN) + lane);
        float4 v5 = __ldg(reinterpret_cast<const float4*>(x + (size_t)e5.x * D_IN) + lane);
        float4 v6 = __ldg(reinterpret_cast<const float4*>(x + (size_t)e6.x * D_IN) + lane);
        float4 v7 = __ldg(reinterpret_cast<const float4*>(x + (size_t)e7.x * D_IN) + lane);
        float w0 = __int_as_float(e0.y), w1 = __int_as_float(e1.y);
        float w2 = __int_as_float(e2.y), w3 = __int_as_float(e3.y);
        float w4 = __int_as_float(e4.y), w5 = __int_as_float(e5.y);
        float w6 = __int_as_float(e6.y), w7 = __int_as_float(e7.y);
        a0.x = fmaf(v0.x, w0, a0.x); a0.y = fmaf(v0.y, w0, a0.y);
        a0.z = fmaf(v0.z, w0, a0.z); a0.w = fmaf(v0.w, w0, a0.w);
        a1.x = fmaf(v1.x, w1, a1.x); a1.y = fmaf(v1.y, w1, a1.y);
        a1.z = fmaf(v1.z, w1, a1.z); a1.w = fmaf(v1.w, w1, a1.w);
        a2.x = fmaf(v2.x, w2, a2.x); a2.y = fmaf(v2.y, w2, a2.y);
        a2.z = fmaf(v2.z, w2, a2.z); a2.w = fmaf(v2.w, w2, a2.w);
        a3.x = fmaf(v3.x, w3, a3.x); a3.y = fmaf(v3.y, w3, a3.y);
        a3.z = fmaf(v3.z, w3, a3.z); a3.w = fmaf(v3.w, w3, a3.w);
        a4.x = fmaf(v4.x, w4, a4.x); a4.y = fmaf(v4.y, w4, a4.y);
        a4.z = fmaf(v4.z, w4, a4.z); a4.w = fmaf(v4.w, w4, a4.w);
        a5.x = fmaf(v5.x, w5, a5.x); a5.y = fmaf(v5.y, w5, a5.y);
        a5.z = fmaf(v5.z, w5, a5.z); a5.w = fmaf(v5.w, w5, a5.w);
        a6.x = fmaf(v6.x, w6, a6.x); a6.y = fmaf(v6.y, w6, a6.y);
        a6.z = fmaf(v6.z, w6, a6.z); a6.w = fmaf(v6.w, w6, a6.w);
        a7.x = fmaf(v7.x, w7, a7.x); a7.y = fmaf(v7.y, w7, a7.y);
        a7.z = fmaf(v7.z, w7, a7.z); a7.w = fmaf(v7.w, w7, a7.w);
        i += 8;
    }
    for (; i < end; ++i) {
        int2 e = __ldg(reinterpret_cast<const int2*>(g_edge) + i);
        float w = __int_as_float(e.y);
        float4 v = __ldg(reinterpret_cast<const float4*>(x + (size_t)e.x * D_IN) + lane);
        a0.x = fmaf(v.x, w, a0.x); a0.y = fmaf(v.y, w, a0.y);
        a0.z = fmaf(v.z, w, a0.z); a0.w = fmaf(v.w, w, a0.w);
    }
    a0.x += (a1.x + a2.x) + (a3.x + a4.x) + (a5.x + a6.x) + a7.x;
    a0.y += (a1.y + a2.y) + (a3.y + a4.y) + (a5.y + a6.y) + a7.y;
    a0.z += (a1.z + a2.z) + (a3.z + a4.z) + (a5.z + a6.z) + a7.z;
    a0.w += (a1.w + a2.w) + (a3.w + a4.w) + (a5.w + a6.w) + a7.w;
    float inv = 1.0f / fmaxf((float)(end - off), 1.0f);
    a0.x *= inv; a0.y *= inv; a0.z *= inv; a0.w *= inv;
    reinterpret_cast<float4*>(g_agg1 + (size_t)n * D_IN)[lane] = a0;
}

// ---------------- layer 1 (f32x2, K-packed, 2ch x 8node blocking) -------------------
#define L1_WPAD 132
#define L1_TILE 64
#define L1_SMEM_BYTES (2 * 128 * L1_WPAD * 4 + 2 * L1_TILE * 128 * 4)  // 200704
__global__ void layer1_kernel(const float* __restrict__ x,
                              const float* __restrict__ Wl,
                              const float* __restrict__ bl,
                              const float* __restrict__ Wr,
                              float* __restrict__ hout) {
    extern __shared__ float sm[];
    float* wl = sm;                             // [128][132] native [j][k]
    float* wr = sm + 128 * L1_WPAD;
    float* fa = sm + 2 * 128 * L1_WPAD;         // [64][128]
    float* fx = fa + L1_TILE * 128;
    int t = threadIdx.x;
    for (int i = t; i < 128 * 128; i += 512) {
        int j = i >> 7, k = i & 127;
        wl[j * L1_WPAD + k] = Wl[i];
        wr[j * L1_WPAD + k] = Wr[i];
    }
    int j = t & 63;                             // channels j, j+64
    int grp = t >> 6;                           // 0..7 -> nodes grp*8 .. grp*8+7
    float bj0 = bl[j], bj1 = bl[j + 64];
    __syncthreads();
    const int NT = (N_NODES + L1_TILE - 1) / L1_TILE;   // 1563 (last tile partial)
    for (int tile = blockIdx.x; tile < NT; tile += gridDim.x) {
        int base = tile * L1_TILE;
        __syncthreads();
        for (int i = t; i < L1_TILE * 128; i += 512) {
            int n = i >> 7, k = i & 127;
            int node = base + n; if (node >= N_NODES) node = N_NODES - 1;
            fa[i] = g_agg1[(size_t)node * 128 + k];
            fx[i] = x[(size_t)node * 128 + k];
        }
        __syncthreads();
        unsigned long long acc0[8], acc1[8];
        #pragma unroll
        for (int n = 0; n < 8; ++n) { acc0[n] = 0ull; acc1[n] = 0ull; }
        const float* fan = fa + grp * 8 * 128;
        const float* fxn = fx + grp * 8 * 128;
        const float* wl0 = wl + j * L1_WPAD;
        const float* wl1 = wl + (j + 64) * L1_WPAD;
        const float* wr0 = wr + j * L1_WPAD;
        const float* wr1 = wr + (j + 64) * L1_WPAD;
        #pragma unroll 4
        for (int k = 0; k < 128; k += 4) {
            ulonglong2 wla = *reinterpret_cast<const ulonglong2*>(wl0 + k);
            ulonglong2 wlb = *reinterpret_cast<const ulonglong2*>(wl1 + k);
            ulonglong2 wra = *reinterpret_cast<const ulonglong2*>(wr0 + k);
            ulonglong2 wrb = *reinterpret_cast<const ulonglong2*>(wr1 + k);
            #pragma unroll
            for (int n = 0; n < 8; ++n) {
                ulonglong2 f_a = *reinterpret_cast<const ulonglong2*>(fan + n * 128 + k);
                ulonglong2 f_x = *reinterpret_cast<const ulonglong2*>(fxn + n * 128 + k);
                acc0[n] = ffma2(wla.x, f_a.x, acc0[n]);
                acc0[n] = ffma2(wla.y, f_a.y, acc0[n]);
                acc0[n] = ffma2(wra.x, f_x.x, acc0[n]);
                acc0[n] = ffma2(wra.y, f_x.y, acc0[n]);
                acc1[n] = ffma2(wlb.x, f_a.x, acc1[n]);
                acc1[n] = ffma2(wlb.y, f_a.y, acc1[n]);
                acc1[n] = ffma2(wrb.x, f_x.x, acc1[n]);
                acc1[n] = ffma2(wrb.y, f_x.y, acc1[n]);
            }
        }
        #pragma unroll
        for (int n = 0; n < 8; ++n) {
            int node = base + grp * 8 + n;
            if (node < N_NODES) {
                float lo, hi;
                unpack2(acc0[n], lo, hi);
                hout[(size_t)node * 128 + j] = fmaxf(lo + hi + bj0, 0.f);
                unpack2(acc1[n], lo, hi);
                hout[(size_t)node * 128 + j + 64] = fmaxf(lo + hi + bj1, 0.f);
            }
        }
    }
}

// ---------------- tmat2 (f32x2, K-packed, fused): t = h@Wl2^T ; r = h@Wr2^T + b2 --------
#define T2_WPAD 132
#define T2_TILE 32
#define T2_SMEM_BYTES (2 * 64 * T2_WPAD * 4 + T2_TILE * 128 * 4)  // 83968
__global__ void tmat2_kernel(const float* __restrict__ h,
                             const float* __restrict__ Wl2,
                             const float* __restrict__ Wr2,
                             const float* __restrict__ b2) {
    extern __shared__ float sm[];
    float* wl = sm;                             // [64][132] native [j][k]
    float* wr = sm + 64 * T2_WPAD;
    float* fh = sm + 2 * 64 * T2_WPAD;          // [32][128]
    int t = threadIdx.x;
    for (int i = t; i < 64 * 128; i += 512) {
        int j = i >> 7, k = i & 127;
        wl[j * T2_WPAD + k] = Wl2[i];
        wr[j * T2_WPAD + k] = Wr2[i];
    }
    int j = t & 63;
    int grp = t >> 6;                           // 0..7 -> nodes grp*4 .. grp*4+3
    float bj = b2[j];
    __syncthreads();
    const int NT = N_NODES / T2_TILE;           // 3125
    for (int tile = blockIdx.x; tile < NT; tile += gridDim.x) {
        int base = tile * T2_TILE;
        __syncthreads();
        for (int i = t; i < T2_TILE * 128; i += 512)
            fh[i] = h[(size_t)base * 128 + i];
        __syncthreads();
        unsigned long long tac[4], rac[4];
        #pragma unroll
        for (int n = 0; n < 4; ++n) { tac[n] = 0ull; rac[n] = 0ull; }
        const float* fn = fh + grp * 4 * 128;
        const float* wlj = wl + j * T2_WPAD;
        const float* wrj = wr + j * T2_WPAD;
        #pragma unroll 4
        for (int k = 0; k < 128; k += 4) {
            ulonglong2 w_l = *reinterpret_cast<const ulonglong2*>(wlj + k);
            ulonglong2 w_r = *reinterpret_cast<const ulonglong2*>(wrj + k);
            #pragma unroll
            for (int n = 0; n < 4; ++n) {
                ulonglong2 f = *reinterpret_cast<const ulonglong2*>(fn + n * 128 + k);
                tac[n] = ffma2(w_l.x, f.x, tac[n]);
                tac[n] = ffma2(w_l.y, f.y, tac[n]);
                rac[n] = ffma2(w_r.x, f.x, rac[n]);
                rac[n] = ffma2(w_r.y, f.y, rac[n]);
            }
        }
        #pragma unroll
        for (int n = 0; n < 4; ++n) {
            int node = base + grp * 4 + n;
            float lo, hi;
            unpack2(tac[n], lo, hi);
            g_t[(size_t)node * 64 + j] = lo + hi;
            unpack2(rac[n], lo, hi);
            g_r[(size_t)node * 64 + j] = lo + hi + bj;
        }
    }
}

// ---------------- gather2 + epilogue: out = mean-agg(t) + r ----------------
// HALF-warp per node (16 lanes x float4 = 64 ch); batches of 8 with edge prefetch
__global__ void gather2_kernel(float* __restrict__ out) {
    int gt = blockIdx.x * blockDim.x + threadIdx.x;
    int n = gt >> 4;
    if (n >= N_NODES) return;
    int sub = gt & 15;
    int off = g_off[n], end = g_off[n + 1];
    float4 a0 = make_float4(0.f, 0.f, 0.f, 0.f);
    float4 a1 = a0, a2 = a0, a3 = a0, a4 = a0, a5 = a0, a6 = a0, a7 = a0;
    int i = off;
    int2 e0, e1, e2, e3, e4, e5, e6, e7;
    bool have = (i + 8 <= end);
    if (have) {
        e0 = __ldg(reinterpret_cast<const int2*>(g_edge) + i + 0);
        e1 = __ldg(reinterpret_cast<const int2*>(g_edge) + i + 1);
        e2 = __ldg(reinterpret_cast<const int2*>(g_edge) + i + 2);
        e3 = __ldg(reinterpret_cast<const int2*>(g_edge) + i + 3);
        e4 = __ldg(reinterpret_cast<const int2*>(g_edge) + i + 4);
        e5 = __ldg(reinterpret_cast<const int2*>(g_edge) + i + 5);
        e6 = __ldg(reinterpret_cast<const int2*>(g_edge) + i + 6);
        e7 = __ldg(reinterpret_cast<const int2*>(g_edge) + i + 7);
    }
    for (; i + 16 <= end; i += 8) {
        int2 f0 = __ldg(reinterpret_cast<const int2*>(g_edge) + i + 8);
        int2 f1 = __ldg(reinterpret_cast<const int2*>(g_edge) + i + 9);
        int2 f2 = __ldg(reinterpret_cast<const int2*>(g_edge) + i + 10);
        int2 f3 = __ldg(reinterpret_cast<const int2*>(g_edge) + i + 11);
        int2 f4 = __ldg(reinterpret_cast<const int2*>(g_edge) + i + 12);
        int2 f5 = __ldg(reinterpret_cast<const int2*>(g_edge) + i + 13);
        int2 f6 = __ldg(reinterpret_cast<const int2*>(g_edge) + i + 14);
        int2 f7 = __ldg(reinterpret_cast<const int2*>(g_edge) + i + 15);
        float4 v0 = __ldg(reinterpret_cast<const float4*>(g_t + (size_t)e0.x * D_OUT) + sub);
        float4 v1 = __ldg(reinterpret_cast<const float4*>(g_t + (size_t)e1.x * D_OUT) + sub);
        float4 v2 = __ldg(reinterpret_cast<const float4*>(g_t + (size_t)e2.x * D_OUT) + sub);
        float4 v3 = __ldg(reinterpret_cast<const float4*>(g_t + (size_t)e3.x * D_OUT) + sub);
        float4 v4 = __ldg(reinterpret_cast<const float4*>(g_t + (size_t)e4.x * D_OUT) + sub);
        float4 v5 = __ldg(reinterpret_cast<const float4*>(g_t + (size_t)e5.x * D_OUT) + sub);
        float4 v6 = __ldg(reinterpret_cast<const float4*>(g_t + (size_t)e6.x * D_OUT) + sub);
        float4 v7 = __ldg(reinterpret_cast<const float4*>(g_t + (size_t)e7.x * D_OUT) + sub);
        float w0 = __int_as_float(e0.y), w1 = __int_as_float(e1.y);
        float w2 = __int_as_float(e2.y), w3 = __int_as_float(e3.y);
        float w4 = __int_as_float(e4.y), w5 = __int_as_float(e5.y);
        float w6 = __int_as_float(e6.y), w7 = __int_as_float(e7.y);
        a0.x = fmaf(v0.x, w0, a0.x); a0.y = fmaf(v0.y, w0, a0.y);
        a0.z = fmaf(v0.z, w0, a0.z); a0.w = fmaf(v0.w, w0, a0.w);
        a1.x = fmaf(v1.x, w1, a1.x); a1.y = fmaf(v1.y, w1, a1.y);
        a1.z = fmaf(v1.z, w1, a1.z); a1.w = fmaf(v1.w, w1, a1.w);
        a2.x = fmaf(v2.x, w2, a2.x); a2.y = fmaf(v2.y, w2, a2.y);
        a2.z = fmaf(v2.z, w2, a2.z); a2.w = fmaf(v2.w, w2, a2.w);
        a3.x = fmaf(v3.x, w3, a3.x); a3.y = fmaf(v3.y, w3, a3.y);
        a3.z = fmaf(v3.z, w3, a3.z); a3.w = fmaf(v3.w, w3, a3.w);
        a4.x = fmaf(v4.x, w4, a4.x); a4.y = fmaf(v4.y, w4, a4.y);
        a4.z = fmaf(v4.z, w4, a4.z); a4.w = fmaf(v4.w, w4, a4.w);
        a5.x = fmaf(v5.x, w5, a5.x); a5.y = fmaf(v5.y, w5, a5.y);
        a5.z = fmaf(v5.z, w5, a5.z); a5.w = fmaf(v5.w, w5, a5.w);
        a6.x = fmaf(v6.x, w6, a6.x); a6.y = fmaf(v6.y, w6, a6.y);
        a6.z = fmaf(v6.z, w6, a6.z); a6.w = fmaf(v6.w, w6, a6.w);
        a7.x = fmaf(v7.x, w7, a7.x); a7.y = fmaf(v7.y, w7, a7.y);
        a7.z = fmaf(v7.z, w7, a7.z); a7.w = fmaf(v7.w, w7, a7.w);
        e0 = f0; e1 = f1; e2 = f2; e3 = f3;
        e4 = f4; e5 = f5; e6 = f6; e7 = f7;
    }
    if (have) {
        float4 v0 = __ldg(reinterpret_cast<const float4*>(g_t + (size_t)e0.x * D_OUT) + sub);
        float4 v1 = __ldg(reinterpret_cast<const float4*>(g_t + (size_t)e1.x * D_OUT) + sub);
        float4 v2 = __ldg(reinterpret_cast<const float4*>(g_t + (size_t)e2.x * D_OUT) + sub);
        float4 v3 = __ldg(reinterpret_cast<const float4*>(g_t + (size_t)e3.x * D_OUT) + sub);
        float4 v4 = __ldg(reinterpret_cast<const float4*>(g_t + (size_t)e4.x * D_OUT) + sub);
        float4 v5 = __ldg(reinterpret_cast<const float4*>(g_t + (size_t)e5.x * D_OUT) + sub);
        float4 v6 = __ldg(reinterpret_cast<const float4*>(g_t + (size_t)e6.x * D_OUT) + sub);
        float4 v7 = __ldg(reinterpret_cast<const float4*>(g_t + (size_t)e7.x * D_OUT) + sub);
        float w0 = __int_as_float(e0.y), w1 = __int_as_float(e1.y);
        float w2 = __int_as_float(e2.y), w3 = __int_as_float(e3.y);
        float w4 = __int_as_float(e4.y), w5 = __int_as_float(e5.y);
        float w6 = __int_as_float(e6.y), w7 = __int_as_float(e7.y);
        a0.x = fmaf(v0.x, w0, a0.x); a0.y = fmaf(v0.y, w0, a0.y);
        a0.z = fmaf(v0.z, w0, a0.z); a0.w = fmaf(v0.w, w0, a0.w);
        a1.x = fmaf(v1.x, w1, a1.x); a1.y = fmaf(v1.y, w1, a1.y);
        a1.z = fmaf(v1.z, w1, a1.z); a1.w = fmaf(v1.w, w1, a1.w);
        a2.x = fmaf(v2.x, w2, a2.x); a2.y = fmaf(v2.y, w2, a2.y);
        a2.z = fmaf(v2.z, w2, a2.z); a2.w = fmaf(v2.w, w2, a2.w);
        a3.x = fmaf(v3.x, w3, a3.x); a3.y = fmaf(v3.y, w3, a3.y);
        a3.z = fmaf(v3.z, w3, a3.z); a3.w = fmaf(v3.w, w3, a3.w);
        a4.x = fmaf(v4.x, w4, a4.x); a4.y = fmaf(v4.y, w4, a4.y);
        a4.z = fmaf(v4.z, w4, a4.z); a4.w = fmaf(v4.w, w4, a4.w);
        a5.x = fmaf(v5.x, w5, a5.x); a5.y = fmaf(v5.y, w5, a5.y);
        a5.z = fmaf(v5.z, w5, a5.z); a5.w = fmaf(v5.w, w5, a5.w);
        a6.x = fmaf(v6.x, w6, a6.x); a6.y = fmaf(v6.y, w6, a6.y);
        a6.z = fmaf(v6.z, w6, a6.z); a6.w = fmaf(v6.w, w6, a6.w);
        a7.x = fmaf(v7.x, w7, a7.x); a7.y = fmaf(v7.y, w7, a7.y);
        a7.z = fmaf(v7.z, w7, a7.z); a7.w = fmaf(v7.w, w7, a7.w);
        i += 8;
    }
    for (; i < end; ++i) {
        int2 e = __ldg(reinterpret_cast<const int2*>(g_edge) + i);
        float w = __int_as_float(e.y);
        float4 v = __ldg(reinterpret_cast<const float4*>(g_t + (size_t)e.x * D_OUT) + sub);
        a0.x = fmaf(v.x, w, a0.x); a0.y = fmaf(v.y, w, a0.y);
        a0.z = fmaf(v.z, w, a0.z); a0.w = fmaf(v.w, w, a0.w);
    }
    a0.x += (a1.x + a2.x) + (a3.x + a4.x) + (a5.x + a6.x) + a7.x;
    a0.y += (a1.y + a2.y) + (a3.y + a4.y) + (a5.y + a6.y) + a7.y;
    a0.z += (a1.z + a2.z) + (a3.z + a4.z) + (a5.z + a6.z) + a7.z;
    a0.w += (a1.w + a2.w) + (a3.w + a4.w) + (a5.w + a6.w) + a7.w;
    float inv = 1.0f / fmaxf((float)(end - off), 1.0f);
    float4 rv = __ldg(reinterpret_cast<const float4*>(g_r + (size_t)n * D_OUT) + sub);
    a0.x = fmaf(a0.x, inv, rv.x);
    a0.y = fmaf(a0.y, inv, rv.y);
    a0.z = fmaf(a0.z, inv, rv.z);
    a0.w = fmaf(a0.w, inv, rv.w);
    reinterpret_cast<float4*>(out + (size_t)n * D_OUT)[sub] = a0;
}

// ---------------- launch ----------------
extern "C" void kernel_launch(void* const* d_in, const int* in_sizes, int n_in,
                              void* d_out, int out_size) {
    (void)in_sizes; (void)n_in;
    const float* x   = (const float*)d_in[0];
    const void*  ei  = d_in[1];                 // int32 or int64, detected on device
    const float* ew  = (const float*)d_in[2];
    const float* Wl1 = (const float*)d_in[3];
    const float* bl1 = (const float*)d_in[4];
    const float* Wr1 = (const float*)d_in[5];
    const float* Wl2 = (const float*)d_in[6];
    const float* bl2 = (const float*)d_in[7];
    const float* Wr2 = (const float*)d_in[8];

    float* hptr;
    float* lptr;
    const size_t full = (size_t)N_NODES * (D_HID + D_OUT);
    if ((size_t)out_size >= full) {
        hptr = (float*)d_out;
        lptr = hptr + (size_t)N_NODES * D_HID;
    } else {
        void* sym = nullptr;
        cudaGetSymbolAddress(&sym, g_h);
        hptr = (float*)sym;
        lptr = (float*)d_out;
    }

    int smcount = 148;
    if (cudaDeviceGetAttribute(&smcount, cudaDevAttrMultiProcessorCount, 0) != cudaSuccess)
        smcount = 148;

    cudaFuncSetAttribute(layer1_kernel,
                         cudaFuncAttributeMaxDynamicSharedMemorySize, L1_SMEM_BYTES);
    cudaFuncSetAttribute(tmat2_kernel,
                         cudaFuncAttributeMaxDynamicSharedMemorySize, T2_SMEM_BYTES);

    detect_zero_kernel<<<NBLK, 256>>>((const int*)ei);     // 1
    hist_kernel<<<N_EDGES / 256, 256>>>(ei);               // 2
    blocksum_kernel<<<NBLK, 256>>>();                      // 3
    offsets_kernel<<<NBLK, 512>>>();                       // 4
    fill_kernel<<<N_EDGES / 256, 256>>>(ei, ew);           // 5
    gather1_kernel<<<(N_NODES * 32 + 255) / 256, 256>>>(x);// 6 <- ncu -s 5 -c 1 target
    layer1_kernel<<<smcount, 512, L1_SMEM_BYTES>>>(x, Wl1, bl1, Wr1, hptr);
    tmat2_kernel<<<2 * smcount, 512, T2_SMEM_BYTES>>>(hptr, Wl2, Wr2, bl2);
    gather2_kernel<<<(N_NODES * 16 + 255) / 256, 256>>>(lptr);
}

// round 12
// speedup vs baseline: 1.1218x; 1.1218x over previous
#include <cuda_runtime.h>
#include <cstddef>

#define N_NODES 100000
#define N_EDGES 3200000
#define D_IN    128
#define D_HID   128
#define D_OUT   64
#define NBLK    391           // ceil(N_NODES / 256)

// ---------------- scratch (no allocation allowed) ----------------
__device__ __align__(16) float g_agg1[(size_t)N_NODES * D_IN];   // mean-agg of x
__device__ __align__(16) float g_t   [(size_t)N_NODES * D_OUT];  // h @ W_l2^T
__device__ __align__(16) float g_r   [(size_t)N_NODES * D_OUT];  // h @ W_r2^T + b2
__device__ __align__(16) float g_h   [(size_t)N_NODES * D_HID];  // fallback h storage
__device__ int  g_deg [N_NODES];
__device__ int  g_off [N_NODES + 1];
__device__ int  g_pos [N_NODES];
__device__ int  g_bsum[NBLK];
__device__ __align__(16) int2 g_edge[N_EDGES];                   // (src, w-bits), dst-grouped
__device__ int  g_idx64;   // 1 if edge_index is int64, 0 if int32

// ---------------- f32x2 helpers ----------------
__device__ __forceinline__ unsigned long long ffma2(unsigned long long a,
                                                    unsigned long long b,
                                                    unsigned long long c) {
    unsigned long long d;
    asm("fma.rn.f32x2 %0, %1, %2, %3;" : "=l"(d) : "l"(a), "l"(b), "l"(c));
    return d;
}
__device__ __forceinline__ void unpack2(unsigned long long d, float& lo, float& hi) {
    asm("mov.b64 {%0, %1}, %2;" : "=f"(lo), "=f"(hi) : "l"(d));
}

// Load edge endpoint #e (src if half==0, dst if half==1) honoring detected dtype.
__device__ __forceinline__ int load_idx(const void* ei, int e, int half, int mode64) {
    if (mode64) {
        long long v = __ldg(reinterpret_cast<const long long*>(ei) +
                            (size_t)half * N_EDGES + e);
        return (int)v;
    } else {
        return __ldg(reinterpret_cast<const int*>(ei) + (size_t)half * N_EDGES + e);
    }
}

// ---------------- dtype detection + zero deg (merged) ----------------
__global__ void detect_zero_kernel(const int* __restrict__ ei_words) {
    int i = blockIdx.x * 256 + threadIdx.x;
    if (i < N_NODES) g_deg[i] = 0;
    if (blockIdx.x == 0) {
        __shared__ int any_nonzero;
        if (threadIdx.x == 0) any_nonzero = 0;
        __syncthreads();
        int acc = 0;
        for (int k = threadIdx.x; k < 4096; k += 256)
            acc |= ei_words[2 * k + 1];
        if (acc) atomicOr(&any_nonzero, 1);
        __syncthreads();
        if (threadIdx.x == 0) g_idx64 = any_nonzero ? 0 : 1;
    }
}

// ---------------- CSR build ----------------
__global__ void hist_kernel(const void* __restrict__ ei) {
    int e = blockIdx.x * blockDim.x + threadIdx.x;
    if (e >= N_EDGES) return;
    int mode64 = g_idx64;
    int d = load_idx(ei, e, 1, mode64);
    if ((unsigned)d < N_NODES) atomicAdd(&g_deg[d], 1);
}

__global__ void blocksum_kernel() {
    __shared__ int s[256];
    int i = blockIdx.x * 256 + threadIdx.x;
    s[threadIdx.x] = (i < N_NODES) ? g_deg[i] : 0;
    __syncthreads();
    for (int d = 128; d > 0; d >>= 1) {
        if (threadIdx.x < d) s[threadIdx.x] += s[threadIdx.x + d];
        __syncthreads();
    }
    if (threadIdx.x == 0) g_bsum[blockIdx.x] = s[0];
}

// merged: every block scans all NBLK block-sums in smem (391 ints), then
// scans its own 256 degrees. 512 threads.
__global__ void offsets_kernel() {
    __shared__ int bs[512];
    __shared__ int s[512];
    int t = threadIdx.x;
    int bv = (t < NBLK) ? g_bsum[t] : 0;
    bs[t] = bv;
    __syncthreads();
    for (int d = 1; d < 512; d <<= 1) {
        int tmp = (t >= d) ? bs[t - d] : 0;
        __syncthreads();
        bs[t] += tmp;
        __syncthreads();
    }
    int bpre = (blockIdx.x == 0) ? 0 : bs[blockIdx.x - 1];
    if (blockIdx.x == 0 && t == 0) g_off[N_NODES] = bs[NBLK - 1];
    int i = blockIdx.x * 256 + t;
    int v = (t < 256 && i < N_NODES) ? g_deg[i] : 0;
    s[t] = v;
    __syncthreads();
    for (int d = 1; d < 512; d <<= 1) {
        int tmp = (t >= d) ? s[t - d] : 0;
        __syncthreads();
        s[t] += tmp;
        __syncthreads();
    }
    if (t < 256 && i < N_NODES) {
        int off = bpre + s[t] - v;
        g_off[i] = off;
        g_pos[i] = off;
    }
}

__global__ void fill_kernel(const void* __restrict__ ei,
                            const float* __restrict__ ew) {
    int e = blockIdx.x * blockDim.x + threadIdx.x;
    if (e >= N_EDGES) return;
    int mode64 = g_idx64;
    int s = load_idx(ei, e, 0, mode64);
    int d = load_idx(ei, e, 1, mode64);
    if ((unsigned)s >= N_NODES || (unsigned)d >= N_NODES) return;
    int p = atomicAdd(&g_pos[d], 1);
    g_edge[p] = make_int2(s, __float_as_int(__ldg(&ew[e])));
}

// ---------------- gather1: agg1[n] = mean over in-edges of x[src]*w ----------------
// one warp per node; lane covers 4 features (float4); batches of 4 with
// cross-batch edge prefetch (edge->data chain pipelined away)
__global__ void gather1_kernel(const float* __restrict__ x) {
    int n = (blockIdx.x * blockDim.x + threadIdx.x) >> 5;
    if (n >= N_NODES) return;
    int lane = threadIdx.x & 31;
    int off = g_off[n], end = g_off[n + 1];
    float4 a0 = make_float4(0.f, 0.f, 0.f, 0.f);
    float4 a1 = a0, a2 = a0, a3 = a0;
    int i = off;
    int2 e0, e1, e2, e3;
    bool have = (i + 4 <= end);
    if (have) {
        e0 = __ldg(reinterpret_cast<const int2*>(g_edge) + i + 0);
        e1 = __ldg(reinterpret_cast<const int2*>(g_edge) + i + 1);
        e2 = __ldg(reinterpret_cast<const int2*>(g_edge) + i + 2);
        e3 = __ldg(reinterpret_cast<const int2*>(g_edge) + i + 3);
    }
    for (; i + 8 <= end; i += 4) {
        // prefetch next batch's edges (independent of current data loads)
        int2 f0 = __ldg(reinterpret_cast<const int2*>(g_edge) + i + 4);
        int2 f1 = __ldg(reinterpret_cast<const int2*>(g_edge) + i + 5);
        int2 f2 = __ldg(reinterpret_cast<const int2*>(g_edge) + i + 6);
        int2 f3 = __ldg(reinterpret_cast<const int2*>(g_edge) + i + 7);
        float4 v0 = __ldg(reinterpret_cast<const float4*>(x + (size_t)e0.x * D_IN) + lane);
        float4 v1 = __ldg(reinterpret_cast<const float4*>(x + (size_t)e1.x * D_IN) + lane);
        float4 v2 = __ldg(reinterpret_cast<const float4*>(x + (size_t)e2.x * D_IN) + lane);
        float4 v3 = __ldg(reinterpret_cast<const float4*>(x + (size_t)e3.x * D_IN) + lane);
        float w0 = __int_as_float(e0.y), w1 = __int_as_float(e1.y);
        float w2 = __int_as_float(e2.y), w3 = __int_as_float(e3.y);
        a0.x = fmaf(v0.x, w0, a0.x); a0.y = fmaf(v0.y, w0, a0.y);
        a0.z = fmaf(v0.z, w0, a0.z); a0.w = fmaf(v0.w, w0, a0.w);
        a1.x = fmaf(v1.x, w1, a1.x); a1.y = fmaf(v1.y, w1, a1.y);
        a1.z = fmaf(v1.z, w1, a1.z); a1.w = fmaf(v1.w, w1, a1.w);
        a2.x = fmaf(v2.x, w2, a2.x); a2.y = fmaf(v2.y, w2, a2.y);
        a2.z = fmaf(v2.z, w2, a2.z); a2.w = fmaf(v2.w, w2, a2.w);
        a3.x = fmaf(v3.x, w3, a3.x); a3.y = fmaf(v3.y, w3, a3.y);
        a3.z = fmaf(v3.z, w3, a3.z); a3.w = fmaf(v3.w, w3, a3.w);
        e0 = f0; e1 = f1; e2 = f2; e3 = f3;
    }
    if (have) {
        // last full prefetched batch [i, i+4)
        float4 v0 = __ldg(reinterpret_cast<const float4*>(x + (size_t)e0.x * D_IN) + lane);
        float4 v1 = __ldg(reinterpret_cast<const float4*>(x + (size_t)e1.x * D_IN) + lane);
        float4 v2 = __ldg(reinterpret_cast<const float4*>(x + (size_t)e2.x * D_IN) + lane);
        float4 v3 = __ldg(reinterpret_cast<const float4*>(x + (size_t)e3.x * D_IN) + lane);
        float w0 = __int_as_float(e0.y), w1 = __int_as_float(e1.y);
        float w2 = __int_as_float(e2.y), w3 = __int_as_float(e3.y);
        a0.x = fmaf(v0.x, w0, a0.x); a0.y = fmaf(v0.y, w0, a0.y);
        a0.z = fmaf(v0.z, w0, a0.z); a0.w = fmaf(v0.w, w0, a0.w);
        a1.x = fmaf(v1.x, w1, a1.x); a1.y = fmaf(v1.y, w1, a1.y);
        a1.z = fmaf(v1.z, w1, a1.z); a1.w = fmaf(v1.w, w1, a1.w);
        a2.x = fmaf(v2.x, w2, a2.x); a2.y = fmaf(v2.y, w2, a2.y);
        a2.z = fmaf(v2.z, w2, a2.z); a2.w = fmaf(v2.w, w2, a2.w);
        a3.x = fmaf(v3.x, w3, a3.x); a3.y = fmaf(v3.y, w3, a3.y);
        a3.z = fmaf(v3.z, w3, a3.z); a3.w = fmaf(v3.w, w3, a3.w);
        i += 4;
    }
    for (; i < end; ++i) {
        int2 e = __ldg(reinterpret_cast<const int2*>(g_edge) + i);
        float w = __int_as_float(e.y);
        float4 v = __ldg(reinterpret_cast<const float4*>(x + (size_t)e.x * D_IN) + lane);
        a0.x = fmaf(v.x, w, a0.x); a0.y = fmaf(v.y, w, a0.y);
        a0.z = fmaf(v.z, w, a0.z); a0.w = fmaf(v.w, w, a0.w);
    }
    a0.x += (a1.x + a2.x) + a3.x;
    a0.y += (a1.y + a2.y) + a3.y;
    a0.z += (a1.z + a2.z) + a3.z;
    a0.w += (a1.w + a2.w) + a3.w;
    float inv = 1.0f / fmaxf((float)(end - off), 1.0f);
    a0.x *= inv; a0.y *= inv; a0.z *= inv; a0.w *= inv;
    reinterpret_cast<float4*>(g_agg1 + (size_t)n * D_IN)[lane] = a0;
}

// ---------------- layer 1 (f32x2, K-packed, 2ch x 8node blocking) -------------------
#define L1_WPAD 132
#define L1_TILE 64
#define L1_SMEM_BYTES (2 * 128 * L1_WPAD * 4 + 2 * L1_TILE * 128 * 4)  // 200704
__global__ void layer1_kernel(const float* __restrict__ x,
                              const float* __restrict__ Wl,
                              const float* __restrict__ bl,
                              const float* __restrict__ Wr,
                              float* __restrict__ hout) {
    extern __shared__ float sm[];
    float* wl = sm;                             // [128][132] native [j][k]
    float* wr = sm + 128 * L1_WPAD;
    float* fa = sm + 2 * 128 * L1_WPAD;         // [64][128]
    float* fx = fa + L1_TILE * 128;
    int t = threadIdx.x;
    for (int i = t; i < 128 * 128; i += 512) {
        int j = i >> 7, k = i & 127;
        wl[j * L1_WPAD + k] = Wl[i];
        wr[j * L1_WPAD + k] = Wr[i];
    }
    int j = t & 63;                             // channels j, j+64
    int grp = t >> 6;                           // 0..7 -> nodes grp*8 .. grp*8+7
    float bj0 = bl[j], bj1 = bl[j + 64];
    __syncthreads();
    const int NT = (N_NODES + L1_TILE - 1) / L1_TILE;   // 1563 (last tile partial)
    for (int tile = blockIdx.x; tile < NT; tile += gridDim.x) {
        int base = tile * L1_TILE;
        __syncthreads();
        for (int i = t; i < L1_TILE * 128; i += 512) {
            int n = i >> 7, k = i & 127;
            int node = base + n; if (node >= N_NODES) node = N_NODES - 1;
            fa[i] = g_agg1[(size_t)node * 128 + k];
            fx[i] = x[(size_t)node * 128 + k];
        }
        __syncthreads();
        unsigned long long acc0[8], acc1[8];
        #pragma unroll
        for (int n = 0; n < 8; ++n) { acc0[n] = 0ull; acc1[n] = 0ull; }
        const float* fan = fa + grp * 8 * 128;
        const float* fxn = fx + grp * 8 * 128;
        const float* wl0 = wl + j * L1_WPAD;
        const float* wl1 = wl + (j + 64) * L1_WPAD;
        const float* wr0 = wr + j * L1_WPAD;
        const float* wr1 = wr + (j + 64) * L1_WPAD;
        #pragma unroll 4
        for (int k = 0; k < 128; k += 4) {
            ulonglong2 wla = *reinterpret_cast<const ulonglong2*>(wl0 + k);
            ulonglong2 wlb = *reinterpret_cast<const ulonglong2*>(wl1 + k);
            ulonglong2 wra = *reinterpret_cast<const ulonglong2*>(wr0 + k);
            ulonglong2 wrb = *reinterpret_cast<const ulonglong2*>(wr1 + k);
            #pragma unroll
            for (int n = 0; n < 8; ++n) {
                ulonglong2 f_a = *reinterpret_cast<const ulonglong2*>(fan + n * 128 + k);
                ulonglong2 f_x = *reinterpret_cast<const ulonglong2*>(fxn + n * 128 + k);
                acc0[n] = ffma2(wla.x, f_a.x, acc0[n]);
                acc0[n] = ffma2(wla.y, f_a.y, acc0[n]);
                acc0[n] = ffma2(wra.x, f_x.x, acc0[n]);
                acc0[n] = ffma2(wra.y, f_x.y, acc0[n]);
                acc1[n] = ffma2(wlb.x, f_a.x, acc1[n]);
                acc1[n] = ffma2(wlb.y, f_a.y, acc1[n]);
                acc1[n] = ffma2(wrb.x, f_x.x, acc1[n]);
                acc1[n] = ffma2(wrb.y, f_x.y, acc1[n]);
            }
        }
        #pragma unroll
        for (int n = 0; n < 8; ++n) {
            int node = base + grp * 8 + n;
            if (node < N_NODES) {
                float lo, hi;
                unpack2(acc0[n], lo, hi);
                hout[(size_t)node * 128 + j] = fmaxf(lo + hi + bj0, 0.f);
                unpack2(acc1[n], lo, hi);
                hout[(size_t)node * 128 + j + 64] = fmaxf(lo + hi + bj1, 0.f);
            }
        }
    }
}

// ---------------- tmat2 (f32x2, K-packed, fused): t = h@Wl2^T ; r = h@Wr2^T + b2 --------
#define T2_WPAD 132
#define T2_TILE 32
#define T2_SMEM_BYTES (2 * 64 * T2_WPAD * 4 + T2_TILE * 128 * 4)  // 83968
__global__ void tmat2_kernel(const float* __restrict__ h,
                             const float* __restrict__ Wl2,
                             const float* __restrict__ Wr2,
                             const float* __restrict__ b2) {
    extern __shared__ float sm[];
    float* wl = sm;                             // [64][132] native [j][k]
    float* wr = sm + 64 * T2_WPAD;
    float* fh = sm + 2 * 64 * T2_WPAD;          // [32][128]
    int t = threadIdx.x;
    for (int i = t; i < 64 * 128; i += 512) {
        int j = i >> 7, k = i & 127;
        wl[j * T2_WPAD + k] = Wl2[i];
        wr[j * T2_WPAD + k] = Wr2[i];
    }
    int j = t & 63;
    int grp = t >> 6;                           // 0..7 -> nodes grp*4 .. grp*4+3
    float bj = b2[j];
    __syncthreads();
    const int NT = N_NODES / T2_TILE;           // 3125
    for (int tile = blockIdx.x; tile < NT; tile += gridDim.x) {
        int base = tile * T2_TILE;
        __syncthreads();
        for (int i = t; i < T2_TILE * 128; i += 512)
            fh[i] = h[(size_t)base * 128 + i];
        __syncthreads();
        unsigned long long tac[4], rac[4];
        #pragma unroll
        for (int n = 0; n < 4; ++n) { tac[n] = 0ull; rac[n] = 0ull; }
        const float* fn = fh + grp * 4 * 128;
        const float* wlj = wl + j * T2_WPAD;
        const float* wrj = wr + j * T2_WPAD;
        #pragma unroll 4
        for (int k = 0; k < 128; k += 4) {
            ulonglong2 w_l = *reinterpret_cast<const ulonglong2*>(wlj + k);
            ulonglong2 w_r = *reinterpret_cast<const ulonglong2*>(wrj + k);
            #pragma unroll
            for (int n = 0; n < 4; ++n) {
                ulonglong2 f = *reinterpret_cast<const ulonglong2*>(fn + n * 128 + k);
                tac[n] = ffma2(w_l.x, f.x, tac[n]);
                tac[n] = ffma2(w_l.y, f.y, tac[n]);
                rac[n] = ffma2(w_r.x, f.x, rac[n]);
                rac[n] = ffma2(w_r.y, f.y, rac[n]);
            }
        }
        #pragma unroll
        for (int n = 0; n < 4; ++n) {
            int node = base + grp * 4 + n;
            float lo, hi;
            unpack2(tac[n], lo, hi);
            g_t[(size_t)node * 64 + j] = lo + hi;
            unpack2(rac[n], lo, hi);
            g_r[(size_t)node * 64 + j] = lo + hi + bj;
        }
    }
}

// ---------------- gather2 + epilogue: out = mean-agg(t) + r ----------------
// HALF-warp per node (16 lanes x float4 = 64 ch); batches of 4 with edge prefetch
__global__ void gather2_kernel(float* __restrict__ out) {
    int gt = blockIdx.x * blockDim.x + threadIdx.x;
    int n = gt >> 4;
    if (n >= N_NODES) return;
    int sub = gt & 15;
    int off = g_off[n], end = g_off[n + 1];
    float4 a0 = make_float4(0.f, 0.f, 0.f, 0.f);
    float4 a1 = a0, a2 = a0, a3 = a0;
    int i = off;
    int2 e0, e1, e2, e3;
    bool have = (i + 4 <= end);
    if (have) {
        e0 = __ldg(reinterpret_cast<const int2*>(g_edge) + i + 0);
        e1 = __ldg(reinterpret_cast<const int2*>(g_edge) + i + 1);
        e2 = __ldg(reinterpret_cast<const int2*>(g_edge) + i + 2);
        e3 = __ldg(reinterpret_cast<const int2*>(g_edge) + i + 3);
    }
    for (; i + 8 <= end; i += 4) {
        int2 f0 = __ldg(reinterpret_cast<const int2*>(g_edge) + i + 4);
        int2 f1 = __ldg(reinterpret_cast<const int2*>(g_edge) + i + 5);
        int2 f2 = __ldg(reinterpret_cast<const int2*>(g_edge) + i + 6);
        int2 f3 = __ldg(reinterpret_cast<const int2*>(g_edge) + i + 7);
        float4 v0 = __ldg(reinterpret_cast<const float4*>(g_t + (size_t)e0.x * D_OUT) + sub);
        float4 v1 = __ldg(reinterpret_cast<const float4*>(g_t + (size_t)e1.x * D_OUT) + sub);
        float4 v2 = __ldg(reinterpret_cast<const float4*>(g_t + (size_t)e2.x * D_OUT) + sub);
        float4 v3 = __ldg(reinterpret_cast<const float4*>(g_t + (size_t)e3.x * D_OUT) + sub);
        float w0 = __int_as_float(e0.y), w1 = __int_as_float(e1.y);
        float w2 = __int_as_float(e2.y), w3 = __int_as_float(e3.y);
        a0.x = fmaf(v0.x, w0, a0.x); a0.y = fmaf(v0.y, w0, a0.y);
        a0.z = fmaf(v0.z, w0, a0.z); a0.w = fmaf(v0.w, w0, a0.w);
        a1.x = fmaf(v1.x, w1, a1.x); a1.y = fmaf(v1.y, w1, a1.y);
        a1.z = fmaf(v1.z, w1, a1.z); a1.w = fmaf(v1.w, w1, a1.w);
        a2.x = fmaf(v2.x, w2, a2.x); a2.y = fmaf(v2.y, w2, a2.y);
        a2.z = fmaf(v2.z, w2, a2.z); a2.w = fmaf(v2.w, w2, a2.w);
        a3.x = fmaf(v3.x, w3, a3.x); a3.y = fmaf(v3.y, w3, a3.y);
        a3.z = fmaf(v3.z, w3, a3.z); a3.w = fmaf(v3.w, w3, a3.w);
        e0 = f0; e1 = f1; e2 = f2; e3 = f3;
    }
    if (have) {
        float4 v0 = __ldg(reinterpret_cast<const float4*>(g_t + (size_t)e0.x * D_OUT) + sub);
        float4 v1 = __ldg(reinterpret_cast<const float4*>(g_t + (size_t)e1.x * D_OUT) + sub);
        float4 v2 = __ldg(reinterpret_cast<const float4*>(g_t + (size_t)e2.x * D_OUT) + sub);
        float4 v3 = __ldg(reinterpret_cast<const float4*>(g_t + (size_t)e3.x * D_OUT) + sub);
        float w0 = __int_as_float(e0.y), w1 = __int_as_float(e1.y);
        float w2 = __int_as_float(e2.y), w3 = __int_as_float(e3.y);
        a0.x = fmaf(v0.x, w0, a0.x); a0.y = fmaf(v0.y, w0, a0.y);
        a0.z = fmaf(v0.z, w0, a0.z); a0.w = fmaf(v0.w, w0, a0.w);
        a1.x = fmaf(v1.x, w1, a1.x); a1.y = fmaf(v1.y, w1, a1.y);
        a1.z = fmaf(v1.z, w1, a1.z); a1.w = fmaf(v1.w, w1, a1.w);
        a2.x = fmaf(v2.x, w2, a2.x); a2.y = fmaf(v2.y, w2, a2.y);
        a2.z = fmaf(v2.z, w2, a2.z); a2.w = fmaf(v2.w, w2, a2.w);
        a3.x = fmaf(v3.x, w3, a3.x); a3.y = fmaf(v3.y, w3, a3.y);
        a3.z = fmaf(v3.z, w3, a3.z); a3.w = fmaf(v3.w, w3, a3.w);
        i += 4;
    }
    for (; i < end; ++i) {
        int2 e = __ldg(reinterpret_cast<const int2*>(g_edge) + i);
        float w = __int_as_float(e.y);
        float4 v = __ldg(reinterpret_cast<const float4*>(g_t + (size_t)e.x * D_OUT) + sub);
        a0.x = fmaf(v.x, w, a0.x); a0.y = fmaf(v.y, w, a0.y);
        a0.z = fmaf(v.z, w, a0.z); a0.w = fmaf(v.w, w, a0.w);
    }
    a0.x += (a1.x + a2.x) + a3.x;
    a0.y += (a1.y + a2.y) + a3.y;
    a0.z += (a1.z + a2.z) + a3.z;
    a0.w += (a1.w + a2.w) + a3.w;
    float inv = 1.0f / fmaxf((float)(end - off), 1.0f);
    float4 rv = __ldg(reinterpret_cast<const float4*>(g_r + (size_t)n * D_OUT) + sub);
    a0.x = fmaf(a0.x, inv, rv.x);
    a0.y = fmaf(a0.y, inv, rv.y);
    a0.z = fmaf(a0.z, inv, rv.z);
    a0.w = fmaf(a0.w, inv, rv.w);
    reinterpret_cast<float4*>(out + (size_t)n * D_OUT)[sub] = a0;
}

// ---------------- launch ----------------
extern "C" void kernel_launch(void* const* d_in, const int* in_sizes, int n_in,
                              void* d_out, int out_size) {
    (void)in_sizes; (void)n_in;
    const float* x   = (const float*)d_in[0];
    const void*  ei  = d_in[1];                 // int32 or int64, detected on device
    const float* ew  = (const float*)d_in[2];
    const float* Wl1 = (const float*)d_in[3];
    const float* bl1 = (const float*)d_in[4];
    const float* Wr1 = (const float*)d_in[5];
    const float* Wl2 = (const float*)d_in[6];
    const float* bl2 = (const float*)d_in[7];
    const float* Wr2 = (const float*)d_in[8];

    float* hptr;
    float* lptr;
    const size_t full = (size_t)N_NODES * (D_HID + D_OUT);
    if ((size_t)out_size >= full) {
        hptr = (float*)d_out;
        lptr = hptr + (size_t)N_NODES * D_HID;
    } else {
        void* sym = nullptr;
        cudaGetSymbolAddress(&sym, g_h);
        hptr = (float*)sym;
        lptr = (float*)d_out;
    }

    int smcount = 148;
    if (cudaDeviceGetAttribute(&smcount, cudaDevAttrMultiProcessorCount, 0) != cudaSuccess)
        smcount = 148;

    cudaFuncSetAttribute(layer1_kernel,
                         cudaFuncAttributeMaxDynamicSharedMemorySize, L1_SMEM_BYTES);
    cudaFuncSetAttribute(tmat2_kernel,
                         cudaFuncAttributeMaxDynamicSharedMemorySize, T2_SMEM_BYTES);

    detect_zero_kernel<<<NBLK, 256>>>((const int*)ei);     // 1
    hist_kernel<<<N_EDGES / 256, 256>>>(ei);               // 2
    blocksum_kernel<<<NBLK, 256>>>();                      // 3
    offsets_kernel<<<NBLK, 512>>>();                       // 4
    fill_kernel<<<N_EDGES / 256, 256>>>(ei, ew);           // 5
    gather1_kernel<<<(N_NODES * 32 + 255) / 256, 256>>>(x);// 6 <- ncu -s 5 -c 1 target
    layer1_kernel<<<smcount, 512, L1_SMEM_BYTES>>>(x, Wl1, bl1, Wr1, hptr);
    tmat2_kernel<<<2 * smcount, 512, T2_SMEM_BYTES>>>(hptr, Wl2, Wr2, bl2);
    gather2_kernel<<<(N_NODES * 16 + 255) / 256, 256>>>(lptr);
}

// round 13
// speedup vs baseline: 1.1334x; 1.0103x over previous
#include <cuda_runtime.h>
#include <cstddef>

#define N_NODES 100000
#define N_EDGES 3200000
#define D_IN    128
#define D_HID   128
#define D_OUT   64
#define NBLK    391           // ceil(N_NODES / 256)

// ---------------- scratch (no allocation allowed) ----------------
__device__ __align__(16) float g_agg1[(size_t)N_NODES * D_IN];   // mean-agg of x
__device__ __align__(16) float g_t   [(size_t)N_NODES * D_OUT];  // h @ W_l2^T
__device__ __align__(16) float g_r   [(size_t)N_NODES * D_OUT];  // h @ W_r2^T + b2
__device__ __align__(16) float g_h   [(size_t)N_NODES * D_HID];  // fallback h storage
__device__ int  g_deg [N_NODES];
__device__ int  g_off [N_NODES + 1];
__device__ int  g_pos [N_NODES];
__device__ int  g_bsum[NBLK];
__device__ __align__(16) int2 g_edge[N_EDGES];                   // (src, w-bits), dst-grouped
__device__ int  g_idx64;   // 1 if edge_index is int64, 0 if int32

// ---------------- f32x2 helpers ----------------
__device__ __forceinline__ unsigned long long ffma2(unsigned long long a,
                                                    unsigned long long b,
                                                    unsigned long long c) {
    unsigned long long d;
    asm("fma.rn.f32x2 %0, %1, %2, %3;" : "=l"(d) : "l"(a), "l"(b), "l"(c));
    return d;
}
__device__ __forceinline__ void unpack2(unsigned long long d, float& lo, float& hi) {
    asm("mov.b64 {%0, %1}, %2;" : "=f"(lo), "=f"(hi) : "l"(d));
}

// Load edge endpoint #e (src if half==0, dst if half==1) honoring detected dtype.
__device__ __forceinline__ int load_idx(const void* ei, int e, int half, int mode64) {
    if (mode64) {
        long long v = __ldg(reinterpret_cast<const long long*>(ei) +
                            (size_t)half * N_EDGES + e);
        return (int)v;
    } else {
        return __ldg(reinterpret_cast<const int*>(ei) + (size_t)half * N_EDGES + e);
    }
}

// Load 4 consecutive indices starting at element base4*4 within half (0=src,1=dst)
__device__ __forceinline__ void load_idx4(const void* ei, int q, int half, int mode64,
                                          int& i0, int& i1, int& i2, int& i3) {
    if (mode64) {
        const longlong2* p = reinterpret_cast<const longlong2*>(
            reinterpret_cast<const long long*>(ei) + (size_t)half * N_EDGES) + q * 2;
        longlong2 a = __ldg(p);
        longlong2 b = __ldg(p + 1);
        i0 = (int)a.x; i1 = (int)a.y; i2 = (int)b.x; i3 = (int)b.y;
    } else {
        int4 d = __ldg(reinterpret_cast<const int4*>(
            reinterpret_cast<const int*>(ei) + (size_t)half * N_EDGES) + q);
        i0 = d.x; i1 = d.y; i2 = d.z; i3 = d.w;
    }
}

// ---------------- dtype detection + zero deg (merged) ----------------
__global__ void detect_zero_kernel(const int* __restrict__ ei_words) {
    int i = blockIdx.x * 256 + threadIdx.x;
    if (i < N_NODES) g_deg[i] = 0;
    if (blockIdx.x == 0) {
        __shared__ int any_nonzero;
        if (threadIdx.x == 0) any_nonzero = 0;
        __syncthreads();
        int acc = 0;
        for (int k = threadIdx.x; k < 4096; k += 256)
            acc |= ei_words[2 * k + 1];
        if (acc) atomicOr(&any_nonzero, 1);
        __syncthreads();
        if (threadIdx.x == 0) g_idx64 = any_nonzero ? 0 : 1;
    }
}

// ---------------- CSR build ----------------
// 4 edges per thread, vectorized index loads
__global__ void hist_kernel(const void* __restrict__ ei) {
    int q = blockIdx.x * blockDim.x + threadIdx.x;
    if (q >= N_EDGES / 4) return;
    int mode64 = g_idx64;
    int d0, d1, d2, d3;
    load_idx4(ei, q, 1, mode64, d0, d1, d2, d3);
    if ((unsigned)d0 < N_NODES) atomicAdd(&g_deg[d0], 1);
    if ((unsigned)d1 < N_NODES) atomicAdd(&g_deg[d1], 1);
    if ((unsigned)d2 < N_NODES) atomicAdd(&g_deg[d2], 1);
    if ((unsigned)d3 < N_NODES) atomicAdd(&g_deg[d3], 1);
}

__global__ void blocksum_kernel() {
    __shared__ int s[256];
    int i = blockIdx.x * 256 + threadIdx.x;
    s[threadIdx.x] = (i < N_NODES) ? g_deg[i] : 0;
    __syncthreads();
    for (int d = 128; d > 0; d >>= 1) {
        if (threadIdx.x < d) s[threadIdx.x] += s[threadIdx.x + d];
        __syncthreads();
    }
    if (threadIdx.x == 0) g_bsum[blockIdx.x] = s[0];
}

// merged: every block scans all NBLK block-sums in smem (391 ints), then
// scans its own 256 degrees. 512 threads.
__global__ void offsets_kernel() {
    __shared__ int bs[512];
    __shared__ int s[512];
    int t = threadIdx.x;
    int bv = (t < NBLK) ? g_bsum[t] : 0;
    bs[t] = bv;
    __syncthreads();
    for (int d = 1; d < 512; d <<= 1) {
        int tmp = (t >= d) ? bs[t - d] : 0;
        __syncthreads();
        bs[t] += tmp;
        __syncthreads();
    }
    int bpre = (blockIdx.x == 0) ? 0 : bs[blockIdx.x - 1];
    if (blockIdx.x == 0 && t == 0) g_off[N_NODES] = bs[NBLK - 1];
    int i = blockIdx.x * 256 + t;
    int v = (t < 256 && i < N_NODES) ? g_deg[i] : 0;
    s[t] = v;
    __syncthreads();
    for (int d = 1; d < 512; d <<= 1) {
        int tmp = (t >= d) ? s[t - d] : 0;
        __syncthreads();
        s[t] += tmp;
        __syncthreads();
    }
    if (t < 256 && i < N_NODES) {
        int off = bpre + s[t] - v;
        g_off[i] = off;
        g_pos[i] = off;
    }
}

// 4 edges per thread, vectorized loads
__global__ void fill_kernel(const void* __restrict__ ei,
                            const float* __restrict__ ew) {
    int q = blockIdx.x * blockDim.x + threadIdx.x;
    if (q >= N_EDGES / 4) return;
    int mode64 = g_idx64;
    int s0, s1, s2, s3, d0, d1, d2, d3;
    load_idx4(ei, q, 0, mode64, s0, s1, s2, s3);
    load_idx4(ei, q, 1, mode64, d0, d1, d2, d3);
    float4 w = __ldg(reinterpret_cast<const float4*>(ew) + q);
    if ((unsigned)s0 < N_NODES && (unsigned)d0 < N_NODES) {
        int p = atomicAdd(&g_pos[d0], 1);
        g_edge[p] = make_int2(s0, __float_as_int(w.x));
    }
    if ((unsigned)s1 < N_NODES && (unsigned)d1 < N_NODES) {
        int p = atomicAdd(&g_pos[d1], 1);
        g_edge[p] = make_int2(s1, __float_as_int(w.y));
    }
    if ((unsigned)s2 < N_NODES && (unsigned)d2 < N_NODES) {
        int p = atomicAdd(&g_pos[d2], 1);
        g_edge[p] = make_int2(s2, __float_as_int(w.z));
    }
    if ((unsigned)s3 < N_NODES && (unsigned)d3 < N_NODES) {
        int p = atomicAdd(&g_pos[d3], 1);
        g_edge[p] = make_int2(s3, __float_as_int(w.w));
    }
}

// ---------------- gather1: agg1[n] = mean over in-edges of x[src]*w ----------------
// one warp per node; lane covers 4 features (float4); batches of 4 with
// cross-batch edge prefetch (edge->data chain pipelined away)
__global__ void gather1_kernel(const float* __restrict__ x) {
    int n = (blockIdx.x * blockDim.x + threadIdx.x) >> 5;
    if (n >= N_NODES) return;
    int lane = threadIdx.x & 31;
    int off = g_off[n], end = g_off[n + 1];
    float4 a0 = make_float4(0.f, 0.f, 0.f, 0.f);
    float4 a1 = a0, a2 = a0, a3 = a0;
    int i = off;
    int2 e0, e1, e2, e3;
    bool have = (i + 4 <= end);
    if (have) {
        e0 = __ldg(reinterpret_cast<const int2*>(g_edge) + i + 0);
        e1 = __ldg(reinterpret_cast<const int2*>(g_edge) + i + 1);
        e2 = __ldg(reinterpret_cast<const int2*>(g_edge) + i + 2);
        e3 = __ldg(reinterpret_cast<const int2*>(g_edge) + i + 3);
    }
    for (; i + 8 <= end; i += 4) {
        int2 f0 = __ldg(reinterpret_cast<const int2*>(g_edge) + i + 4);
        int2 f1 = __ldg(reinterpret_cast<const int2*>(g_edge) + i + 5);
        int2 f2 = __ldg(reinterpret_cast<const int2*>(g_edge) + i + 6);
        int2 f3 = __ldg(reinterpret_cast<const int2*>(g_edge) + i + 7);
        float4 v0 = __ldg(reinterpret_cast<const float4*>(x + (size_t)e0.x * D_IN) + lane);
        float4 v1 = __ldg(reinterpret_cast<const float4*>(x + (size_t)e1.x * D_IN) + lane);
        float4 v2 = __ldg(reinterpret_cast<const float4*>(x + (size_t)e2.x * D_IN) + lane);
        float4 v3 = __ldg(reinterpret_cast<const float4*>(x + (size_t)e3.x * D_IN) + lane);
        float w0 = __int_as_float(e0.y), w1 = __int_as_float(e1.y);
        float w2 = __int_as_float(e2.y), w3 = __int_as_float(e3.y);
        a0.x = fmaf(v0.x, w0, a0.x); a0.y = fmaf(v0.y, w0, a0.y);
        a0.z = fmaf(v0.z, w0, a0.z); a0.w = fmaf(v0.w, w0, a0.w);
        a1.x = fmaf(v1.x, w1, a1.x); a1.y = fmaf(v1.y, w1, a1.y);
        a1.z = fmaf(v1.z, w1, a1.z); a1.w = fmaf(v1.w, w1, a1.w);
        a2.x = fmaf(v2.x, w2, a2.x); a2.y = fmaf(v2.y, w2, a2.y);
        a2.z = fmaf(v2.z, w2, a2.z); a2.w = fmaf(v2.w, w2, a2.w);
        a3.x = fmaf(v3.x, w3, a3.x); a3.y = fmaf(v3.y, w3, a3.y);
        a3.z = fmaf(v3.z, w3, a3.z); a3.w = fmaf(v3.w, w3, a3.w);
        e0 = f0; e1 = f1; e2 = f2; e3 = f3;
    }
    if (have) {
        float4 v0 = __ldg(reinterpret_cast<const float4*>(x + (size_t)e0.x * D_IN) + lane);
        float4 v1 = __ldg(reinterpret_cast<const float4*>(x + (size_t)e1.x * D_IN) + lane);
        float4 v2 = __ldg(reinterpret_cast<const float4*>(x + (size_t)e2.x * D_IN) + lane);
        float4 v3 = __ldg(reinterpret_cast<const float4*>(x + (size_t)e3.x * D_IN) + lane);
        float w0 = __int_as_float(e0.y), w1 = __int_as_float(e1.y);
        float w2 = __int_as_float(e2.y), w3 = __int_as_float(e3.y);
        a0.x = fmaf(v0.x, w0, a0.x); a0.y = fmaf(v0.y, w0, a0.y);
        a0.z = fmaf(v0.z, w0, a0.z); a0.w = fmaf(v0.w, w0, a0.w);
        a1.x = fmaf(v1.x, w1, a1.x); a1.y = fmaf(v1.y, w1, a1.y);
        a1.z = fmaf(v1.z, w1, a1.z); a1.w = fmaf(v1.w, w1, a1.w);
        a2.x = fmaf(v2.x, w2, a2.x); a2.y = fmaf(v2.y, w2, a2.y);
        a2.z = fmaf(v2.z, w2, a2.z); a2.w = fmaf(v2.w, w2, a2.w);
        a3.x = fmaf(v3.x, w3, a3.x); a3.y = fmaf(v3.y, w3, a3.y);
        a3.z = fmaf(v3.z, w3, a3.z); a3.w = fmaf(v3.w, w3, a3.w);
        i += 4;
    }
    for (; i < end; ++i) {
        int2 e = __ldg(reinterpret_cast<const int2*>(g_edge) + i);
        float w = __int_as_float(e.y);
        float4 v = __ldg(reinterpret_cast<const float4*>(x + (size_t)e.x * D_IN) + lane);
        a0.x = fmaf(v.x, w, a0.x); a0.y = fmaf(v.y, w, a0.y);
        a0.z = fmaf(v.z, w, a0.z); a0.w = fmaf(v.w, w, a0.w);
    }
    a0.x += (a1.x + a2.x) + a3.x;
    a0.y += (a1.y + a2.y) + a3.y;
    a0.z += (a1.z + a2.z) + a3.z;
    a0.w += (a1.w + a2.w) + a3.w;
    float inv = 1.0f / fmaxf((float)(end - off), 1.0f);
    a0.x *= inv; a0.y *= inv; a0.z *= inv; a0.w *= inv;
    reinterpret_cast<float4*>(g_agg1 + (size_t)n * D_IN)[lane] = a0;
}

// ---------------- layer 1 (f32x2, K-packed, 2ch x 8node blocking) -------------------
#define L1_WPAD 132
#define L1_TILE 64
#define L1_SMEM_BYTES (2 * 128 * L1_WPAD * 4 + 2 * L1_TILE * 128 * 4)  // 200704
__global__ void layer1_kernel(const float* __restrict__ x,
                              const float* __restrict__ Wl,
                              const float* __restrict__ bl,
                              const float* __restrict__ Wr,
                              float* __restrict__ hout) {
    extern __shared__ float sm[];
    float* wl = sm;                             // [128][132] native [j][k]
    float* wr = sm + 128 * L1_WPAD;
    float* fa = sm + 2 * 128 * L1_WPAD;         // [64][128]
    float* fx = fa + L1_TILE * 128;
    int t = threadIdx.x;
    for (int i = t; i < 128 * 128; i += 512) {
        int j = i >> 7, k = i & 127;
        wl[j * L1_WPAD + k] = Wl[i];
        wr[j * L1_WPAD + k] = Wr[i];
    }
    int j = t & 63;                             // channels j, j+64
    int grp = t >> 6;                           // 0..7 -> nodes grp*8 .. grp*8+7
    float bj0 = bl[j], bj1 = bl[j + 64];
    __syncthreads();
    const int NT = (N_NODES + L1_TILE - 1) / L1_TILE;   // 1563 (last tile partial)
    for (int tile = blockIdx.x; tile < NT; tile += gridDim.x) {
        int base = tile * L1_TILE;
        __syncthreads();
        // float4-vectorized smem fill: 64 nodes x 32 float4
        for (int i = t; i < L1_TILE * 32; i += 512) {
            int n = i >> 5, k4 = i & 31;
            int node = base + n; if (node >= N_NODES) node = N_NODES - 1;
            reinterpret_cast<float4*>(fa)[i] =
                *reinterpret_cast<const float4*>(&g_agg1[(size_t)node * 128 + k4 * 4]);
            reinterpret_cast<float4*>(fx)[i] =
                __ldg(reinterpret_cast<const float4*>(&x[(size_t)node * 128 + k4 * 4]));
        }
        __syncthreads();
        unsigned long long acc0[8], acc1[8];
        #pragma unroll
        for (int n = 0; n < 8; ++n) { acc0[n] = 0ull; acc1[n] = 0ull; }
        const float* fan = fa + grp * 8 * 128;
        const float* fxn = fx + grp * 8 * 128;
        const float* wl0 = wl + j * L1_WPAD;
        const float* wl1 = wl + (j + 64) * L1_WPAD;
        const float* wr0 = wr + j * L1_WPAD;
        const float* wr1 = wr + (j + 64) * L1_WPAD;
        #pragma unroll 4
        for (int k = 0; k < 128; k += 4) {
            ulonglong2 wla = *reinterpret_cast<const ulonglong2*>(wl0 + k);
            ulonglong2 wlb = *reinterpret_cast<const ulonglong2*>(wl1 + k);
            ulonglong2 wra = *reinterpret_cast<const ulonglong2*>(wr0 + k);
            ulonglong2 wrb = *reinterpret_cast<const ulonglong2*>(wr1 + k);
            #pragma unroll
            for (int n = 0; n < 8; ++n) {
                ulonglong2 f_a = *reinterpret_cast<const ulonglong2*>(fan + n * 128 + k);
                ulonglong2 f_x = *reinterpret_cast<const ulonglong2*>(fxn + n * 128 + k);
                acc0[n] = ffma2(wla.x, f_a.x, acc0[n]);
                acc0[n] = ffma2(wla.y, f_a.y, acc0[n]);
                acc0[n] = ffma2(wra.x, f_x.x, acc0[n]);
                acc0[n] = ffma2(wra.y, f_x.y, acc0[n]);
                acc1[n] = ffma2(wlb.x, f_a.x, acc1[n]);
                acc1[n] = ffma2(wlb.y, f_a.y, acc1[n]);
                acc1[n] = ffma2(wrb.x, f_x.x, acc1[n]);
                acc1[n] = ffma2(wrb.y, f_x.y, acc1[n]);
            }
        }
        #pragma unroll
        for (int n = 0; n < 8; ++n) {
            int node = base + grp * 8 + n;
            if (node < N_NODES) {
                float lo, hi;
                unpack2(acc0[n], lo, hi);
                hout[(size_t)node * 128 + j] = fmaxf(lo + hi + bj0, 0.f);
                unpack2(acc1[n], lo, hi);
                hout[(size_t)node * 128 + j + 64] = fmaxf(lo + hi + bj1, 0.f);
            }
        }
    }
}

// ---------------- tmat2 (f32x2, K-packed, fused): t = h@Wl2^T ; r = h@Wr2^T + b2 --------
#define T2_WPAD 132
#define T2_TILE 32
#define T2_SMEM_BYTES (2 * 64 * T2_WPAD * 4 + T2_TILE * 128 * 4)  // 83968
__global__ void tmat2_kernel(const float* __restrict__ h,
                             const float* __restrict__ Wl2,
                             const float* __restrict__ Wr2,
                             const float* __restrict__ b2) {
    extern __shared__ float sm[];
    float* wl = sm;                             // [64][132] native [j][k]
    float* wr = sm + 64 * T2_WPAD;
    float* fh = sm + 2 * 64 * T2_WPAD;          // [32][128]
    int t = threadIdx.x;
    for (int i = t; i < 64 * 128; i += 512) {
        int j = i >> 7, k = i & 127;
        wl[j * T2_WPAD + k] = Wl2[i];
        wr[j * T2_WPAD + k] = Wr2[i];
    }
    int j = t & 63;
    int grp = t >> 6;                           // 0..7 -> nodes grp*4 .. grp*4+3
    float bj = b2[j];
    __syncthreads();
    const int NT = N_NODES / T2_TILE;           // 3125
    for (int tile = blockIdx.x; tile < NT; tile += gridDim.x) {
        int base = tile * T2_TILE;
        __syncthreads();
        // float4-vectorized smem fill: 32*128 floats = 1024 float4
        for (int i = t; i < T2_TILE * 32; i += 512)
            reinterpret_cast<float4*>(fh)[i] =
                *reinterpret_cast<const float4*>(&h[(size_t)base * 128 + i * 4]);
        __syncthreads();
        unsigned long long tac[4], rac[4];
        #pragma unroll
        for (int n = 0; n < 4; ++n) { tac[n] = 0ull; rac[n] = 0ull; }
        const float* fn = fh + grp * 4 * 128;
        const float* wlj = wl + j * T2_WPAD;
        const float* wrj = wr + j * T2_WPAD;
        #pragma unroll 4
        for (int k = 0; k < 128; k += 4) {
            ulonglong2 w_l = *reinterpret_cast<const ulonglong2*>(wlj + k);
            ulonglong2 w_r = *reinterpret_cast<const ulonglong2*>(wrj + k);
            #pragma unroll
            for (int n = 0; n < 4; ++n) {
                ulonglong2 f = *reinterpret_cast<const ulonglong2*>(fn + n * 128 + k);
                tac[n] = ffma2(w_l.x, f.x, tac[n]);
                tac[n] = ffma2(w_l.y, f.y, tac[n]);
                rac[n] = ffma2(w_r.x, f.x, rac[n]);
                rac[n] = ffma2(w_r.y, f.y, rac[n]);
            }
        }
        #pragma unroll
        for (int n = 0; n < 4; ++n) {
            int node = base + grp * 4 + n;
            float lo, hi;
            unpack2(tac[n], lo, hi);
            g_t[(size_t)node * 64 + j] = lo + hi;
            unpack2(rac[n], lo, hi);
            g_r[(size_t)node * 64 + j] = lo + hi + bj;
        }
    }
}

// ---------------- gather2 + epilogue: out = mean-agg(t) + r ----------------
// HALF-warp per node (16 lanes x float4 = 64 ch); batches of 4 with edge prefetch
__global__ void gather2_kernel(float* __restrict__ out) {
    int gt = blockIdx.x * blockDim.x + threadIdx.x;
    int n = gt >> 4;
    if (n >= N_NODES) return;
    int sub = gt & 15;
    int off = g_off[n], end = g_off[n + 1];
    // hoist independent r load above the edge loop (overlaps gather latency)
    float4 rv = __ldg(reinterpret_cast<const float4*>(g_r + (size_t)n * D_OUT) + sub);
    float4 a0 = make_float4(0.f, 0.f, 0.f, 0.f);
    float4 a1 = a0, a2 = a0, a3 = a0;
    int i = off;
    int2 e0, e1, e2, e3;
    bool have = (i + 4 <= end);
    if (have) {
        e0 = __ldg(reinterpret_cast<const int2*>(g_edge) + i + 0);
        e1 = __ldg(reinterpret_cast<const int2*>(g_edge) + i + 1);
        e2 = __ldg(reinterpret_cast<const int2*>(g_edge) + i + 2);
        e3 = __ldg(reinterpret_cast<const int2*>(g_edge) + i + 3);
    }
    for (; i + 8 <= end; i += 4) {
        int2 f0 = __ldg(reinterpret_cast<const int2*>(g_edge) + i + 4);
        int2 f1 = __ldg(reinterpret_cast<const int2*>(g_edge) + i + 5);
        int2 f2 = __ldg(reinterpret_cast<const int2*>(g_edge) + i + 6);
        int2 f3 = __ldg(reinterpret_cast<const int2*>(g_edge) + i + 7);
        float4 v0 = __ldg(reinterpret_cast<const float4*>(g_t + (size_t)e0.x * D_OUT) + sub);
        float4 v1 = __ldg(reinterpret_cast<const float4*>(g_t + (size_t)e1.x * D_OUT) + sub);
        float4 v2 = __ldg(reinterpret_cast<const float4*>(g_t + (size_t)e2.x * D_OUT) + sub);
        float4 v3 = __ldg(reinterpret_cast<const float4*>(g_t + (size_t)e3.x * D_OUT) + sub);
        float w0 = __int_as_float(e0.y), w1 = __int_as_float(e1.y);
        float w2 = __int_as_float(e2.y), w3 = __int_as_float(e3.y);
        a0.x = fmaf(v0.x, w0, a0.x); a0.y = fmaf(v0.y, w0, a0.y);
        a0.z = fmaf(v0.z, w0, a0.z); a0.w = fmaf(v0.w, w0, a0.w);
        a1.x = fmaf(v1.x, w1, a1.x); a1.y = fmaf(v1.y, w1, a1.y);
        a1.z = fmaf(v1.z, w1, a1.z); a1.w = fmaf(v1.w, w1, a1.w);
        a2.x = fmaf(v2.x, w2, a2.x); a2.y = fmaf(v2.y, w2, a2.y);
        a2.z = fmaf(v2.z, w2, a2.z); a2.w = fmaf(v2.w, w2, a2.w);
        a3.x = fmaf(v3.x, w3, a3.x); a3.y = fmaf(v3.y, w3, a3.y);
        a3.z = fmaf(v3.z, w3, a3.z); a3.w = fmaf(v3.w, w3, a3.w);
        e0 = f0; e1 = f1; e2 = f2; e3 = f3;
    }
    if (have) {
        float4 v0 = __ldg(reinterpret_cast<const float4*>(g_t + (size_t)e0.x * D_OUT) + sub);
        float4 v1 = __ldg(reinterpret_cast<const float4*>(g_t + (size_t)e1.x * D_OUT) + sub);
        float4 v2 = __ldg(reinterpret_cast<const float4*>(g_t + (size_t)e2.x * D_OUT) + sub);
        float4 v3 = __ldg(reinterpret_cast<const float4*>(g_t + (size_t)e3.x * D_OUT) + sub);
        float w0 = __int_as_float(e0.y), w1 = __int_as_float(e1.y);
        float w2 = __int_as_float(e2.y), w3 = __int_as_float(e3.y);
        a0.x = fmaf(v0.x, w0, a0.x); a0.y = fmaf(v0.y, w0, a0.y);
        a0.z = fmaf(v0.z, w0, a0.z); a0.w = fmaf(v0.w, w0, a0.w);
        a1.x = fmaf(v1.x, w1, a1.x); a1.y = fmaf(v1.y, w1, a1.y);
        a1.z = fmaf(v1.z, w1, a1.z); a1.w = fmaf(v1.w, w1, a1.w);
        a2.x = fmaf(v2.x, w2, a2.x); a2.y = fmaf(v2.y, w2, a2.y);
        a2.z = fmaf(v2.z, w2, a2.z); a2.w = fmaf(v2.w, w2, a2.w);
        a3.x = fmaf(v3.x, w3, a3.x); a3.y = fmaf(v3.y, w3, a3.y);
        a3.z = fmaf(v3.z, w3, a3.z); a3.w = fmaf(v3.w, w3, a3.w);
        i += 4;
    }
    for (; i < end; ++i) {
        int2 e = __ldg(reinterpret_cast<const int2*>(g_edge) + i);
        float w = __int_as_float(e.y);
        float4 v = __ldg(reinterpret_cast<const float4*>(g_t + (size_t)e.x * D_OUT) + sub);
        a0.x = fmaf(v.x, w, a0.x); a0.y = fmaf(v.y, w, a0.y);
        a0.z = fmaf(v.z, w, a0.z); a0.w = fmaf(v.w, w, a0.w);
    }
    a0.x += (a1.x + a2.x) + a3.x;
    a0.y += (a1.y + a2.y) + a3.y;
    a0.z += (a1.z + a2.z) + a3.z;
    a0.w += (a1.w + a2.w) + a3.w;
    float inv = 1.0f / fmaxf((float)(end - off), 1.0f);
    a0.x = fmaf(a0.x, inv, rv.x);
    a0.y = fmaf(a0.y, inv, rv.y);
    a0.z = fmaf(a0.z, inv, rv.z);
    a0.w = fmaf(a0.w, inv, rv.w);
    reinterpret_cast<float4*>(out + (size_t)n * D_OUT)[sub] = a0;
}

// ---------------- launch ----------------
extern "C" void kernel_launch(void* const* d_in, const int* in_sizes, int n_in,
                              void* d_out, int out_size) {
    (void)in_sizes; (void)n_in;
    const float* x   = (const float*)d_in[0];
    const void*  ei  = d_in[1];                 // int32 or int64, detected on device
    const float* ew  = (const float*)d_in[2];
    const float* Wl1 = (const float*)d_in[3];
    const float* bl1 = (const float*)d_in[4];
    const float* Wr1 = (const float*)d_in[5];
    const float* Wl2 = (const float*)d_in[6];
    const float* bl2 = (const float*)d_in[7];
    const float* Wr2 = (const float*)d_in[8];

    float* hptr;
    float* lptr;
    const size_t full = (size_t)N_NODES * (D_HID + D_OUT);
    if ((size_t)out_size >= full) {
        hptr = (float*)d_out;
        lptr = hptr + (size_t)N_NODES * D_HID;
    } else {
        void* sym = nullptr;
        cudaGetSymbolAddress(&sym, g_h);
        hptr = (float*)sym;
        lptr = (float*)d_out;
    }

    int smcount = 148;
    if (cudaDeviceGetAttribute(&smcount, cudaDevAttrMultiProcessorCount, 0) != cudaSuccess)
        smcount = 148;

    cudaFuncSetAttribute(layer1_kernel,
                         cudaFuncAttributeMaxDynamicSharedMemorySize, L1_SMEM_BYTES);
    cudaFuncSetAttribute(tmat2_kernel,
                         cudaFuncAttributeMaxDynamicSharedMemorySize, T2_SMEM_BYTES);

    detect_zero_kernel<<<NBLK, 256>>>((const int*)ei);       // 1
    hist_kernel<<<N_EDGES / 4 / 256, 256>>>(ei);             // 2 (4 edges/thread)
    blocksum_kernel<<<NBLK, 256>>>();                        // 3
    offsets_kernel<<<NBLK, 512>>>();                         // 4
    fill_kernel<<<N_EDGES / 4 / 256, 256>>>(ei, ew);         // 5 (4 edges/thread)
    gather1_kernel<<<(N_NODES * 32 + 255) / 256, 256>>>(x);  // 6
    layer1_kernel<<<smcount, 512, L1_SMEM_BYTES>>>(x, Wl1, bl1, Wr1, hptr);
    tmat2_kernel<<<2 * smcount, 512, T2_SMEM_BYTES>>>(hptr, Wl2, Wr2, bl2);
    gather2_kernel<<<(N_NODES * 16 + 255) / 256, 256>>>(lptr);
}

// round 14
// speedup vs baseline: 1.3046x; 1.1510x over previous
#include <cuda_runtime.h>
#include <cstddef>

#define N_NODES 100000
#define N_EDGES 3200000
#define D_IN    128
#define D_HID   128
#define D_OUT   64
#define NBLK    391           // ceil(N_NODES / 256)

// ---------------- scratch (no allocation allowed) ----------------
__device__ __align__(16) float g_agg1[(size_t)N_NODES * D_IN];   // mean-agg of x
__device__ __align__(16) float g_t   [(size_t)N_NODES * D_OUT];  // h @ W_l2^T
__device__ __align__(16) float g_r   [(size_t)N_NODES * D_OUT];  // h @ W_r2^T + b2
__device__ __align__(16) float g_h   [(size_t)N_NODES * D_HID];  // fallback h storage
__device__ int  g_deg [N_NODES];
__device__ int  g_off [N_NODES + 1];
__device__ int  g_pos [N_NODES];
__device__ int  g_bsum[NBLK];
__device__ __align__(16) int2 g_edge[N_EDGES];                   // (src, w-bits), dst-grouped
__device__ int  g_idx64;   // 1 if edge_index is int64, 0 if int32

// ---------------- f32x2 helpers ----------------
__device__ __forceinline__ unsigned long long ffma2(unsigned long long a,
                                                    unsigned long long b,
                                                    unsigned long long c) {
    unsigned long long d;
    asm("fma.rn.f32x2 %0, %1, %2, %3;" : "=l"(d) : "l"(a), "l"(b), "l"(c));
    return d;
}
__device__ __forceinline__ void unpack2(unsigned long long d, float& lo, float& hi) {
    asm("mov.b64 {%0, %1}, %2;" : "=f"(lo), "=f"(hi) : "l"(d));
}
// round fp32 -> tf32 (round-to-nearest; unbiased)
__device__ __forceinline__ float tf32r(float v) {
    unsigned u;
    asm("cvt.rna.tf32.f32 %0, %1;" : "=r"(u) : "f"(v));
    return __uint_as_float(u);
}
__device__ __forceinline__ void mma_tf32(float& c0, float& c1, float& c2, float& c3,
                                         unsigned a0, unsigned a1, unsigned a2, unsigned a3,
                                         unsigned b0, unsigned b1) {
    asm("mma.sync.aligned.m16n8k8.row.col.f32.tf32.tf32.f32 "
        "{%0,%1,%2,%3}, {%4,%5,%6,%7}, {%8,%9}, {%0,%1,%2,%3};"
        : "+f"(c0), "+f"(c1), "+f"(c2), "+f"(c3)
        : "r"(a0), "r"(a1), "r"(a2), "r"(a3), "r"(b0), "r"(b1));
}

// Load edge endpoint #e (src if half==0, dst if half==1) honoring detected dtype.
__device__ __forceinline__ int load_idx(const void* ei, int e, int half, int mode64) {
    if (mode64) {
        long long v = __ldg(reinterpret_cast<const long long*>(ei) +
                            (size_t)half * N_EDGES + e);
        return (int)v;
    } else {
        return __ldg(reinterpret_cast<const int*>(ei) + (size_t)half * N_EDGES + e);
    }
}

// Load 4 consecutive indices (element group q) within half (0=src,1=dst)
__device__ __forceinline__ void load_idx4(const void* ei, int q, int half, int mode64,
                                          int& i0, int& i1, int& i2, int& i3) {
    if (mode64) {
        const longlong2* p = reinterpret_cast<const longlong2*>(
            reinterpret_cast<const long long*>(ei) + (size_t)half * N_EDGES) + q * 2;
        longlong2 a = __ldg(p);
        longlong2 b = __ldg(p + 1);
        i0 = (int)a.x; i1 = (int)a.y; i2 = (int)b.x; i3 = (int)b.y;
    } else {
        int4 d = __ldg(reinterpret_cast<const int4*>(
            reinterpret_cast<const int*>(ei) + (size_t)half * N_EDGES) + q);
        i0 = d.x; i1 = d.y; i2 = d.z; i3 = d.w;
    }
}

// ---------------- dtype detection + zero deg (merged) ----------------
__global__ void detect_zero_kernel(const int* __restrict__ ei_words) {
    int i = blockIdx.x * 256 + threadIdx.x;
    if (i < N_NODES) g_deg[i] = 0;
    if (blockIdx.x == 0) {
        __shared__ int any_nonzero;
        if (threadIdx.x == 0) any_nonzero = 0;
        __syncthreads();
        int acc = 0;
        for (int k = threadIdx.x; k < 4096; k += 256)
            acc |= ei_words[2 * k + 1];
        if (acc) atomicOr(&any_nonzero, 1);
        __syncthreads();
        if (threadIdx.x == 0) g_idx64 = any_nonzero ? 0 : 1;
    }
}

// ---------------- CSR build ----------------
__global__ void hist_kernel(const void* __restrict__ ei) {
    int q = blockIdx.x * blockDim.x + threadIdx.x;
    if (q >= N_EDGES / 4) return;
    int mode64 = g_idx64;
    int d0, d1, d2, d3;
    load_idx4(ei, q, 1, mode64, d0, d1, d2, d3);
    if ((unsigned)d0 < N_NODES) atomicAdd(&g_deg[d0], 1);
    if ((unsigned)d1 < N_NODES) atomicAdd(&g_deg[d1], 1);
    if ((unsigned)d2 < N_NODES) atomicAdd(&g_deg[d2], 1);
    if ((unsigned)d3 < N_NODES) atomicAdd(&g_deg[d3], 1);
}

__global__ void blocksum_kernel() {
    __shared__ int s[256];
    int i = blockIdx.x * 256 + threadIdx.x;
    s[threadIdx.x] = (i < N_NODES) ? g_deg[i] : 0;
    __syncthreads();
    for (int d = 128; d > 0; d >>= 1) {
        if (threadIdx.x < d) s[threadIdx.x] += s[threadIdx.x + d];
        __syncthreads();
    }
    if (threadIdx.x == 0) g_bsum[blockIdx.x] = s[0];
}

__global__ void offsets_kernel() {
    __shared__ int bs[512];
    __shared__ int s[512];
    int t = threadIdx.x;
    int bv = (t < NBLK) ? g_bsum[t] : 0;
    bs[t] = bv;
    __syncthreads();
    for (int d = 1; d < 512; d <<= 1) {
        int tmp = (t >= d) ? bs[t - d] : 0;
        __syncthreads();
        bs[t] += tmp;
        __syncthreads();
    }
    int bpre = (blockIdx.x == 0) ? 0 : bs[blockIdx.x - 1];
    if (blockIdx.x == 0 && t == 0) g_off[N_NODES] = bs[NBLK - 1];
    int i = blockIdx.x * 256 + t;
    int v = (t < 256 && i < N_NODES) ? g_deg[i] : 0;
    s[t] = v;
    __syncthreads();
    for (int d = 1; d < 512; d <<= 1) {
        int tmp = (t >= d) ? s[t - d] : 0;
        __syncthreads();
        s[t] += tmp;
        __syncthreads();
    }
    if (t < 256 && i < N_NODES) {
        int off = bpre + s[t] - v;
        g_off[i] = off;
        g_pos[i] = off;
    }
}

__global__ void fill_kernel(const void* __restrict__ ei,
                            const float* __restrict__ ew) {
    int q = blockIdx.x * blockDim.x + threadIdx.x;
    if (q >= N_EDGES / 4) return;
    int mode64 = g_idx64;
    int s0, s1, s2, s3, d0, d1, d2, d3;
    load_idx4(ei, q, 0, mode64, s0, s1, s2, s3);
    load_idx4(ei, q, 1, mode64, d0, d1, d2, d3);
    float4 w = __ldg(reinterpret_cast<const float4*>(ew) + q);
    if ((unsigned)s0 < N_NODES && (unsigned)d0 < N_NODES) {
        int p = atomicAdd(&g_pos[d0], 1);
        g_edge[p] = make_int2(s0, __float_as_int(w.x));
    }
    if ((unsigned)s1 < N_NODES && (unsigned)d1 < N_NODES) {
        int p = atomicAdd(&g_pos[d1], 1);
        g_edge[p] = make_int2(s1, __float_as_int(w.y));
    }
    if ((unsigned)s2 < N_NODES && (unsigned)d2 < N_NODES) {
        int p = atomicAdd(&g_pos[d2], 1);
        g_edge[p] = make_int2(s2, __float_as_int(w.z));
    }
    if ((unsigned)s3 < N_NODES && (unsigned)d3 < N_NODES) {
        int p = atomicAdd(&g_pos[d3], 1);
        g_edge[p] = make_int2(s3, __float_as_int(w.w));
    }
}

// ---------------- gather1: agg1[n] = mean over in-edges of x[src]*w ----------------
__global__ void gather1_kernel(const float* __restrict__ x) {
    int n = (blockIdx.x * blockDim.x + threadIdx.x) >> 5;
    if (n >= N_NODES) return;
    int lane = threadIdx.x & 31;
    int off = g_off[n], end = g_off[n + 1];
    float4 a0 = make_float4(0.f, 0.f, 0.f, 0.f);
    float4 a1 = a0, a2 = a0, a3 = a0;
    int i = off;
    int2 e0, e1, e2, e3;
    bool have = (i + 4 <= end);
    if (have) {
        e0 = __ldg(reinterpret_cast<const int2*>(g_edge) + i + 0);
        e1 = __ldg(reinterpret_cast<const int2*>(g_edge) + i + 1);
        e2 = __ldg(reinterpret_cast<const int2*>(g_edge) + i + 2);
        e3 = __ldg(reinterpret_cast<const int2*>(g_edge) + i + 3);
    }
    for (; i + 8 <= end; i += 4) {
        int2 f0 = __ldg(reinterpret_cast<const int2*>(g_edge) + i + 4);
        int2 f1 = __ldg(reinterpret_cast<const int2*>(g_edge) + i + 5);
        int2 f2 = __ldg(reinterpret_cast<const int2*>(g_edge) + i + 6);
        int2 f3 = __ldg(reinterpret_cast<const int2*>(g_edge) + i + 7);
        float4 v0 = __ldg(reinterpret_cast<const float4*>(x + (size_t)e0.x * D_IN) + lane);
        float4 v1 = __ldg(reinterpret_cast<const float4*>(x + (size_t)e1.x * D_IN) + lane);
        float4 v2 = __ldg(reinterpret_cast<const float4*>(x + (size_t)e2.x * D_IN) + lane);
        float4 v3 = __ldg(reinterpret_cast<const float4*>(x + (size_t)e3.x * D_IN) + lane);
        float w0 = __int_as_float(e0.y), w1 = __int_as_float(e1.y);
        float w2 = __int_as_float(e2.y), w3 = __int_as_float(e3.y);
        a0.x = fmaf(v0.x, w0, a0.x); a0.y = fmaf(v0.y, w0, a0.y);
        a0.z = fmaf(v0.z, w0, a0.z); a0.w = fmaf(v0.w, w0, a0.w);
        a1.x = fmaf(v1.x, w1, a1.x); a1.y = fmaf(v1.y, w1, a1.y);
        a1.z = fmaf(v1.z, w1, a1.z); a1.w = fmaf(v1.w, w1, a1.w);
        a2.x = fmaf(v2.x, w2, a2.x); a2.y = fmaf(v2.y, w2, a2.y);
        a2.z = fmaf(v2.z, w2, a2.z); a2.w = fmaf(v2.w, w2, a2.w);
        a3.x = fmaf(v3.x, w3, a3.x); a3.y = fmaf(v3.y, w3, a3.y);
        a3.z = fmaf(v3.z, w3, a3.z); a3.w = fmaf(v3.w, w3, a3.w);
        e0 = f0; e1 = f1; e2 = f2; e3 = f3;
    }
    if (have) {
        float4 v0 = __ldg(reinterpret_cast<const float4*>(x + (size_t)e0.x * D_IN) + lane);
        float4 v1 = __ldg(reinterpret_cast<const float4*>(x + (size_t)e1.x * D_IN) + lane);
        float4 v2 = __ldg(reinterpret_cast<const float4*>(x + (size_t)e2.x * D_IN) + lane);
        float4 v3 = __ldg(reinterpret_cast<const float4*>(x + (size_t)e3.x * D_IN) + lane);
        float w0 = __int_as_float(e0.y), w1 = __int_as_float(e1.y);
        float w2 = __int_as_float(e2.y), w3 = __int_as_float(e3.y);
        a0.x = fmaf(v0.x, w0, a0.x); a0.y = fmaf(v0.y, w0, a0.y);
        a0.z = fmaf(v0.z, w0, a0.z); a0.w = fmaf(v0.w, w0, a0.w);
        a1.x = fmaf(v1.x, w1, a1.x); a1.y = fmaf(v1.y, w1, a1.y);
        a1.z = fmaf(v1.z, w1, a1.z); a1.w = fmaf(v1.w, w1, a1.w);
        a2.x = fmaf(v2.x, w2, a2.x); a2.y = fmaf(v2.y, w2, a2.y);
        a2.z = fmaf(v2.z, w2, a2.z); a2.w = fmaf(v2.w, w2, a2.w);
        a3.x = fmaf(v3.x, w3, a3.x); a3.y = fmaf(v3.y, w3, a3.y);
        a3.z = fmaf(v3.z, w3, a3.z); a3.w = fmaf(v3.w, w3, a3.w);
        i += 4;
    }
    for (; i < end; ++i) {
        int2 e = __ldg(reinterpret_cast<const int2*>(g_edge) + i);
        float w = __int_as_float(e.y);
        float4 v = __ldg(reinterpret_cast<const float4*>(x + (size_t)e.x * D_IN) + lane);
        a0.x = fmaf(v.x, w, a0.x); a0.y = fmaf(v.y, w, a0.y);
        a0.z = fmaf(v.z, w, a0.z); a0.w = fmaf(v.w, w, a0.w);
    }
    a0.x += (a1.x + a2.x) + a3.x;
    a0.y += (a1.y + a2.y) + a3.y;
    a0.z += (a1.z + a2.z) + a3.z;
    a0.w += (a1.w + a2.w) + a3.w;
    float inv = 1.0f / fmaxf((float)(end - off), 1.0f);
    a0.x *= inv; a0.y *= inv; a0.z *= inv; a0.w *= inv;
    reinterpret_cast<float4*>(g_agg1 + (size_t)n * D_IN)[lane] = a0;
}

// ---------------- layer 1 (tensor-core tf32 mma): h = relu([agg1|x] @ [Wl|Wr]^T + b) ----
// Single GEMM view: F[n][k], k in [0,256): k<128 -> agg1, k>=128 -> x.
//                   W[j][k]: k<128 -> Wl[j][k], k>=128 -> Wr[j][k-128].
// Block tile: 64 nodes x 128 ch, K=256. 16 warps: warp (mw = w>>2, nw = w&3)
// computes m16 (nodes mw*16..) x n32 (ch nw*32..) via 4 x m16n8k8 per k-step.
// smem holds F and W pre-swizzled into per-lane mma fragment order:
//   F_frag[(m_tile*32 + ks)*32 + L][4] : {a0,a1,a2,a3}   (LDS.128, conflict-free)
//   W_frag[(n_tile*32 + ks)*32 + L][2] : {b0,b1}         (LDS.64,  conflict-free)
// Values pre-rounded to tf32 with cvt.rna (unbiased).
#define LTC_WFLOATS (16 * 32 * 32 * 2)     // 32768 floats = 128 KB
#define LTC_FFLOATS (4 * 32 * 32 * 4)      // 16384 floats = 64 KB
#define LTC_SMEM_BYTES ((LTC_WFLOATS + LTC_FFLOATS) * 4)   // 196608
__global__ void layer1_tc_kernel(const float* __restrict__ x,
                                 const float* __restrict__ Wl,
                                 const float* __restrict__ bl,
                                 const float* __restrict__ Wr,
                                 float* __restrict__ hout) {
    extern __shared__ float sm[];
    float* Wf = sm;                    // fragment-order weights
    float* Ff = sm + LTC_WFLOATS;      // fragment-order features
    int t = threadIdx.x;

    // ---- one-time: stage weights in fragment order (tf32-rounded) ----
    // slots: (j 0..127) x (k4 0..63): 8192 float4 reads
    for (int it = t; it < 128 * 64; it += 512) {
        int j = it >> 6, k4 = it & 63;
        int k0 = k4 * 4;
        float4 v = (k0 < 128)
            ? __ldg(reinterpret_cast<const float4*>(Wl + (size_t)j * 128 + k0))
            : __ldg(reinterpret_cast<const float4*>(Wr + (size_t)j * 128 + (k0 - 128)));
        int n_tile = j >> 3, g = j & 7;
        int ks = k0 >> 3, slot = (k0 & 7) >> 2;
        float* dst = Wf + ((n_tile * 32 + ks) * 32) * 2 + slot;
        int Lb = g * 4;
        dst[(Lb + 0) * 2] = tf32r(v.x);
        dst[(Lb + 1) * 2] = tf32r(v.y);
        dst[(Lb + 2) * 2] = tf32r(v.z);
        dst[(Lb + 3) * 2] = tf32r(v.w);
    }
    int warp = t >> 5, L = t & 31;
    int mw = warp >> 2, nw = warp & 3;
    int g = L >> 2, tg = L & 3;
    __syncthreads();

    const int NT = (N_NODES + 63) / 64;      // 1563 (last tile partial)
    for (int tile = blockIdx.x; tile < NT; tile += gridDim.x) {
        int base = tile * 64;
        __syncthreads();
        // ---- stage features in fragment order: (nn 0..63) x (k4 0..63) ----
        for (int it = t; it < 64 * 64; it += 512) {
            int nn = it >> 6, k4 = it & 63;
            int node = base + nn; if (node >= N_NODES) node = N_NODES - 1;
            int k0 = k4 * 4;
            float4 v = (k0 < 128)
                ? *reinterpret_cast<const float4*>(g_agg1 + (size_t)node * 128 + k0)
                : __ldg(reinterpret_cast<const float4*>(x + (size_t)node * 128 + (k0 - 128)));
            int m_tile = nn >> 4, r = nn & 15;
            int gg = r & 7, rowhi = r >> 3;
            int ks = k0 >> 3, colhi = (k0 & 7) >> 2;
            int f = rowhi + 2 * colhi;
            float* dst = Ff + ((m_tile * 32 + ks) * 32) * 4 + f;
            int Lb = gg * 4;
            dst[(Lb + 0) * 4] = tf32r(v.x);
            dst[(Lb + 1) * 4] = tf32r(v.y);
            dst[(Lb + 2) * 4] = tf32r(v.z);
            dst[(Lb + 3) * 4] = tf32r(v.w);
        }
        __syncthreads();
        // ---- mma mainloop ----
        float c[4][4];
        #pragma unroll
        for (int nt = 0; nt < 4; ++nt)
            c[nt][0] = c[nt][1] = c[nt][2] = c[nt][3] = 0.f;
        const float* fa = Ff + (mw * 32) * 128 + L * 4;       // + ks*128
        #pragma unroll 4
        for (int ks = 0; ks < 32; ++ks) {
            float4 av = *reinterpret_cast<const float4*>(fa + ks * 128);
            unsigned a0 = __float_as_uint(av.x), a1 = __float_as_uint(av.y);
            unsigned a2 = __float_as_uint(av.z), a3 = __float_as_uint(av.w);
            #pragma unroll
            for (int nt = 0; nt < 4; ++nt) {
                const float* fb = Wf + ((nw * 4 + nt) * 32 + ks) * 64 + L * 2;
                float2 bv = *reinterpret_cast<const float2*>(fb);
                mma_tf32(c[nt][0], c[nt][1], c[nt][2], c[nt][3],
                         a0, a1, a2, a3,
                         __float_as_uint(bv.x), __float_as_uint(bv.y));
            }
        }
        // ---- epilogue: bias + relu, write h ----
        int n0 = base + mw * 16 + g;
        int n1 = n0 + 8;
        #pragma unroll
        for (int nt = 0; nt < 4; ++nt) {
            int j0 = nw * 32 + nt * 8 + tg * 2;
            float b0 = __ldg(&bl[j0]), b1 = __ldg(&bl[j0 + 1]);
            if (n0 < N_NODES) {
                float2 o = make_float2(fmaxf(c[nt][0] + b0, 0.f),
                                       fmaxf(c[nt][1] + b1, 0.f));
                *reinterpret_cast<float2*>(&hout[(size_t)n0 * 128 + j0]) = o;
            }
            if (n1 < N_NODES) {
                float2 o = make_float2(fmaxf(c[nt][2] + b0, 0.f),
                                       fmaxf(c[nt][3] + b1, 0.f));
                *reinterpret_cast<float2*>(&hout[(size_t)n1 * 128 + j0]) = o;
            }
        }
    }
}

// ---------------- tmat2 (f32x2, K-packed, fused): t = h@Wl2^T ; r = h@Wr2^T + b2 --------
#define T2_WPAD 132
#define T2_TILE 32
#define T2_SMEM_BYTES (2 * 64 * T2_WPAD * 4 + T2_TILE * 128 * 4)  // 83968
__global__ void tmat2_kernel(const float* __restrict__ h,
                             const float* __restrict__ Wl2,
                             const float* __restrict__ Wr2,
                             const float* __restrict__ b2) {
    extern __shared__ float sm[];
    float* wl = sm;                             // [64][132] native [j][k]
    float* wr = sm + 64 * T2_WPAD;
    float* fh = sm + 2 * 64 * T2_WPAD;          // [32][128]
    int t = threadIdx.x;
    for (int i = t; i < 64 * 128; i += 512) {
        int j = i >> 7, k = i & 127;
        wl[j * T2_WPAD + k] = Wl2[i];
        wr[j * T2_WPAD + k] = Wr2[i];
    }
    int j = t & 63;
    int grp = t >> 6;                           // 0..7 -> nodes grp*4 .. grp*4+3
    float bj = b2[j];
    __syncthreads();
    const int NT = N_NODES / T2_TILE;           // 3125
    for (int tile = blockIdx.x; tile < NT; tile += gridDim.x) {
        int base = tile * T2_TILE;
        __syncthreads();
        for (int i = t; i < T2_TILE * 32; i += 512)
            reinterpret_cast<float4*>(fh)[i] =
                *reinterpret_cast<const float4*>(&h[(size_t)base * 128 + i * 4]);
        __syncthreads();
        unsigned long long tac[4], rac[4];
        #pragma unroll
        for (int n = 0; n < 4; ++n) { tac[n] = 0ull; rac[n] = 0ull; }
        const float* fn = fh + grp * 4 * 128;
        const float* wlj = wl + j * T2_WPAD;
        const float* wrj = wr + j * T2_WPAD;
        #pragma unroll 4
        for (int k = 0; k < 128; k += 4) {
            ulonglong2 w_l = *reinterpret_cast<const ulonglong2*>(wlj + k);
            ulonglong2 w_r = *reinterpret_cast<const ulonglong2*>(wrj + k);
            #pragma unroll
            for (int n = 0; n < 4; ++n) {
                ulonglong2 f = *reinterpret_cast<const ulonglong2*>(fn + n * 128 + k);
                tac[n] = ffma2(w_l.x, f.x, tac[n]);
                tac[n] = ffma2(w_l.y, f.y, tac[n]);
                rac[n] = ffma2(w_r.x, f.x, rac[n]);
                rac[n] = ffma2(w_r.y, f.y, rac[n]);
            }
        }
        #pragma unroll
        for (int n = 0; n < 4; ++n) {
            int node = base + grp * 4 + n;
            float lo, hi;
            unpack2(tac[n], lo, hi);
            g_t[(size_t)node * 64 + j] = lo + hi;
            unpack2(rac[n], lo, hi);
            g_r[(size_t)node * 64 + j] = lo + hi + bj;
        }
    }
}

// ---------------- gather2 + epilogue: out = mean-agg(t) + r ----------------
__global__ void gather2_kernel(float* __restrict__ out) {
    int gt = blockIdx.x * blockDim.x + threadIdx.x;
    int n = gt >> 4;
    if (n >= N_NODES) return;
    int sub = gt & 15;
    int off = g_off[n], end = g_off[n + 1];
    float4 rv = __ldg(reinterpret_cast<const float4*>(g_r + (size_t)n * D_OUT) + sub);
    float4 a0 = make_float4(0.f, 0.f, 0.f, 0.f);
    float4 a1 = a0, a2 = a0, a3 = a0;
    int i = off;
    int2 e0, e1, e2, e3;
    bool have = (i + 4 <= end);
    if (have) {
        e0 = __ldg(reinterpret_cast<const int2*>(g_edge) + i + 0);
        e1 = __ldg(reinterpret_cast<const int2*>(g_edge) + i + 1);
        e2 = __ldg(reinterpret_cast<const int2*>(g_edge) + i + 2);
        e3 = __ldg(reinterpret_cast<const int2*>(g_edge) + i + 3);
    }
    for (; i + 8 <= end; i += 4) {
        int2 f0 = __ldg(reinterpret_cast<const int2*>(g_edge) + i + 4);
        int2 f1 = __ldg(reinterpret_cast<const int2*>(g_edge) + i + 5);
        int2 f2 = __ldg(reinterpret_cast<const int2*>(g_edge) + i + 6);
        int2 f3 = __ldg(reinterpret_cast<const int2*>(g_edge) + i + 7);
        float4 v0 = __ldg(reinterpret_cast<const float4*>(g_t + (size_t)e0.x * D_OUT) + sub);
        float4 v1 = __ldg(reinterpret_cast<const float4*>(g_t + (size_t)e1.x * D_OUT) + sub);
        float4 v2 = __ldg(reinterpret_cast<const float4*>(g_t + (size_t)e2.x * D_OUT) + sub);
        float4 v3 = __ldg(reinterpret_cast<const float4*>(g_t + (size_t)e3.x * D_OUT) + sub);
        float w0 = __int_as_float(e0.y), w1 = __int_as_float(e1.y);
        float w2 = __int_as_float(e2.y), w3 = __int_as_float(e3.y);
        a0.x = fmaf(v0.x, w0, a0.x); a0.y = fmaf(v0.y, w0, a0.y);
        a0.z = fmaf(v0.z, w0, a0.z); a0.w = fmaf(v0.w, w0, a0.w);
        a1.x = fmaf(v1.x, w1, a1.x); a1.y = fmaf(v1.y, w1, a1.y);
        a1.z = fmaf(v1.z, w1, a1.z); a1.w = fmaf(v1.w, w1, a1.w);
        a2.x = fmaf(v2.x, w2, a2.x); a2.y = fmaf(v2.y, w2, a2.y);
        a2.z = fmaf(v2.z, w2, a2.z); a2.w = fmaf(v2.w, w2, a2.w);
        a3.x = fmaf(v3.x, w3, a3.x); a3.y = fmaf(v3.y, w3, a3.y);
        a3.z = fmaf(v3.z, w3, a3.z); a3.w = fmaf(v3.w, w3, a3.w);
        e0 = f0; e1 = f1; e2 = f2; e3 = f3;
    }
    if (have) {
        float4 v0 = __ldg(reinterpret_cast<const float4*>(g_t + (size_t)e0.x * D_OUT) + sub);
        float4 v1 = __ldg(reinterpret_cast<const float4*>(g_t + (size_t)e1.x * D_OUT) + sub);
        float4 v2 = __ldg(reinterpret_cast<const float4*>(g_t + (size_t)e2.x * D_OUT) + sub);
        float4 v3 = __ldg(reinterpret_cast<const float4*>(g_t + (size_t)e3.x * D_OUT) + sub);
        float w0 = __int_as_float(e0.y), w1 = __int_as_float(e1.y);
        float w2 = __int_as_float(e2.y), w3 = __int_as_float(e3.y);
        a0.x = fmaf(v0.x, w0, a0.x); a0.y = fmaf(v0.y, w0, a0.y);
        a0.z = fmaf(v0.z, w0, a0.z); a0.w = fmaf(v0.w, w0, a0.w);
        a1.x = fmaf(v1.x, w1, a1.x); a1.y = fmaf(v1.y, w1, a1.y);
        a1.z = fmaf(v1.z, w1, a1.z); a1.w = fmaf(v1.w, w1, a1.w);
        a2.x = fmaf(v2.x, w2, a2.x); a2.y = fmaf(v2.y, w2, a2.y);
        a2.z = fmaf(v2.z, w2, a2.z); a2.w = fmaf(v2.w, w2, a2.w);
        a3.x = fmaf(v3.x, w3, a3.x); a3.y = fmaf(v3.y, w3, a3.y);
        a3.z = fmaf(v3.z, w3, a3.z); a3.w = fmaf(v3.w, w3, a3.w);
        i += 4;
    }
    for (; i < end; ++i) {
        int2 e = __ldg(reinterpret_cast<const int2*>(g_edge) + i);
        float w = __int_as_float(e.y);
        float4 v = __ldg(reinterpret_cast<const float4*>(g_t + (size_t)e.x * D_OUT) + sub);
        a0.x = fmaf(v.x, w, a0.x); a0.y = fmaf(v.y, w, a0.y);
        a0.z = fmaf(v.z, w, a0.z); a0.w = fmaf(v.w, w, a0.w);
    }
    a0.x += (a1.x + a2.x) + a3.x;
    a0.y += (a1.y + a2.y) + a3.y;
    a0.z += (a1.z + a2.z) + a3.z;
    a0.w += (a1.w + a2.w) + a3.w;
    float inv = 1.0f / fmaxf((float)(end - off), 1.0f);
    a0.x = fmaf(a0.x, inv, rv.x);
    a0.y = fmaf(a0.y, inv, rv.y);
    a0.z = fmaf(a0.z, inv, rv.z);
    a0.w = fmaf(a0.w, inv, rv.w);
    reinterpret_cast<float4*>(out + (size_t)n * D_OUT)[sub] = a0;
}

// ---------------- launch ----------------
extern "C" void kernel_launch(void* const* d_in, const int* in_sizes, int n_in,
                              void* d_out, int out_size) {
    (void)in_sizes; (void)n_in;
    const float* x   = (const float*)d_in[0];
    const void*  ei  = d_in[1];                 // int32 or int64, detected on device
    const float* ew  = (const float*)d_in[2];
    const float* Wl1 = (const float*)d_in[3];
    const float* bl1 = (const float*)d_in[4];
    const float* Wr1 = (const float*)d_in[5];
    const float* Wl2 = (const float*)d_in[6];
    const float* bl2 = (const float*)d_in[7];
    const float* Wr2 = (const float*)d_in[8];

    float* hptr;
    float* lptr;
    const size_t full = (size_t)N_NODES * (D_HID + D_OUT);
    if ((size_t)out_size >= full) {
        hptr = (float*)d_out;
        lptr = hptr + (size_t)N_NODES * D_HID;
    } else {
        void* sym = nullptr;
        cudaGetSymbolAddress(&sym, g_h);
        hptr = (float*)sym;
        lptr = (float*)d_out;
    }

    int smcount = 148;
    if (cudaDeviceGetAttribute(&smcount, cudaDevAttrMultiProcessorCount, 0) != cudaSuccess)
        smcount = 148;

    cudaFuncSetAttribute(layer1_tc_kernel,
                         cudaFuncAttributeMaxDynamicSharedMemorySize, LTC_SMEM_BYTES);
    cudaFuncSetAttribute(tmat2_kernel,
                         cudaFuncAttributeMaxDynamicSharedMemorySize, T2_SMEM_BYTES);

    detect_zero_kernel<<<NBLK, 256>>>((const int*)ei);       // 1
    hist_kernel<<<N_EDGES / 4 / 256, 256>>>(ei);             // 2
    blocksum_kernel<<<NBLK, 256>>>();                        // 3
    offsets_kernel<<<NBLK, 512>>>();                         // 4
    fill_kernel<<<N_EDGES / 4 / 256, 256>>>(ei, ew);         // 5
    gather1_kernel<<<(N_NODES * 32 + 255) / 256, 256>>>(x);  // 6
    layer1_tc_kernel<<<smcount, 512, LTC_SMEM_BYTES>>>(x, Wl1, bl1, Wr1, hptr);
    tmat2_kernel<<<2 * smcount, 512, T2_SMEM_BYTES>>>(hptr, Wl2, Wr2, bl2);
    gather2_kernel<<<(N_NODES * 16 + 255) / 256, 256>>>(lptr);
}

// round 15
// speedup vs baseline: 1.4225x; 1.0904x over previous
#include <cuda_runtime.h>
#include <cstddef>

#define N_NODES 100000
#define N_EDGES 3200000
#define D_IN    128
#define D_HID   128
#define D_OUT   64
#define NBLK    391           // ceil(N_NODES / 256)

// ---------------- scratch (no allocation allowed) ----------------
__device__ __align__(16) float g_agg1[(size_t)N_NODES * D_IN];   // mean-agg of x
__device__ __align__(16) float g_t   [(size_t)N_NODES * D_OUT];  // h @ W_l2^T
__device__ __align__(16) float g_r   [(size_t)N_NODES * D_OUT];  // h @ W_r2^T + b2
__device__ __align__(16) float g_h   [(size_t)N_NODES * D_HID];  // fallback h storage
__device__ int  g_deg [N_NODES];
__device__ int  g_off [N_NODES + 1];
__device__ int  g_pos [N_NODES];
__device__ int  g_bsum[NBLK];
__device__ __align__(16) int2 g_edge[N_EDGES];                   // (src, w-bits), dst-grouped
__device__ int  g_idx64;   // 1 if edge_index is int64, 0 if int32

// ---------------- helpers ----------------
// round fp32 -> tf32 (round-to-nearest; unbiased)
__device__ __forceinline__ float tf32r(float v) {
    unsigned u;
    asm("cvt.rna.tf32.f32 %0, %1;" : "=r"(u) : "f"(v));
    return __uint_as_float(u);
}
__device__ __forceinline__ void mma_tf32(float& c0, float& c1, float& c2, float& c3,
                                         unsigned a0, unsigned a1, unsigned a2, unsigned a3,
                                         unsigned b0, unsigned b1) {
    asm("mma.sync.aligned.m16n8k8.row.col.f32.tf32.tf32.f32 "
        "{%0,%1,%2,%3}, {%4,%5,%6,%7}, {%8,%9}, {%0,%1,%2,%3};"
        : "+f"(c0), "+f"(c1), "+f"(c2), "+f"(c3)
        : "r"(a0), "r"(a1), "r"(a2), "r"(a3), "r"(b0), "r"(b1));
}

// Load edge endpoint #e (src if half==0, dst if half==1) honoring detected dtype.
__device__ __forceinline__ int load_idx(const void* ei, int e, int half, int mode64) {
    if (mode64) {
        long long v = __ldg(reinterpret_cast<const long long*>(ei) +
                            (size_t)half * N_EDGES + e);
        return (int)v;
    } else {
        return __ldg(reinterpret_cast<const int*>(ei) + (size_t)half * N_EDGES + e);
    }
}

// Load 4 consecutive indices (element group q) within half (0=src,1=dst)
__device__ __forceinline__ void load_idx4(const void* ei, int q, int half, int mode64,
                                          int& i0, int& i1, int& i2, int& i3) {
    if (mode64) {
        const longlong2* p = reinterpret_cast<const longlong2*>(
            reinterpret_cast<const long long*>(ei) + (size_t)half * N_EDGES) + q * 2;
        longlong2 a = __ldg(p);
        longlong2 b = __ldg(p + 1);
        i0 = (int)a.x; i1 = (int)a.y; i2 = (int)b.x; i3 = (int)b.y;
    } else {
        int4 d = __ldg(reinterpret_cast<const int4*>(
            reinterpret_cast<const int*>(ei) + (size_t)half * N_EDGES) + q);
        i0 = d.x; i1 = d.y; i2 = d.z; i3 = d.w;
    }
}

// ---------------- dtype detection + zero deg (merged) ----------------
__global__ void detect_zero_kernel(const int* __restrict__ ei_words) {
    int i = blockIdx.x * 256 + threadIdx.x;
    if (i < N_NODES) g_deg[i] = 0;
    if (blockIdx.x == 0) {
        __shared__ int any_nonzero;
        if (threadIdx.x == 0) any_nonzero = 0;
        __syncthreads();
        int acc = 0;
        for (int k = threadIdx.x; k < 4096; k += 256)
            acc |= ei_words[2 * k + 1];
        if (acc) atomicOr(&any_nonzero, 1);
        __syncthreads();
        if (threadIdx.x == 0) g_idx64 = any_nonzero ? 0 : 1;
    }
}

// ---------------- CSR build ----------------
__global__ void hist_kernel(const void* __restrict__ ei) {
    int q = blockIdx.x * blockDim.x + threadIdx.x;
    if (q >= N_EDGES / 4) return;
    int mode64 = g_idx64;
    int d0, d1, d2, d3;
    load_idx4(ei, q, 1, mode64, d0, d1, d2, d3);
    if ((unsigned)d0 < N_NODES) atomicAdd(&g_deg[d0], 1);
    if ((unsigned)d1 < N_NODES) atomicAdd(&g_deg[d1], 1);
    if ((unsigned)d2 < N_NODES) atomicAdd(&g_deg[d2], 1);
    if ((unsigned)d3 < N_NODES) atomicAdd(&g_deg[d3], 1);
}

__global__ void blocksum_kernel() {
    __shared__ int s[256];
    int i = blockIdx.x * 256 + threadIdx.x;
    s[threadIdx.x] = (i < N_NODES) ? g_deg[i] : 0;
    __syncthreads();
    for (int d = 128; d > 0; d >>= 1) {
        if (threadIdx.x < d) s[threadIdx.x] += s[threadIdx.x + d];
        __syncthreads();
    }
    if (threadIdx.x == 0) g_bsum[blockIdx.x] = s[0];
}

__global__ void offsets_kernel() {
    __shared__ int bs[512];
    __shared__ int s[512];
    int t = threadIdx.x;
    int bv = (t < NBLK) ? g_bsum[t] : 0;
    bs[t] = bv;
    __syncthreads();
    for (int d = 1; d < 512; d <<= 1) {
        int tmp = (t >= d) ? bs[t - d] : 0;
        __syncthreads();
        bs[t] += tmp;
        __syncthreads();
    }
    int bpre = (blockIdx.x == 0) ? 0 : bs[blockIdx.x - 1];
    if (blockIdx.x == 0 && t == 0) g_off[N_NODES] = bs[NBLK - 1];
    int i = blockIdx.x * 256 + t;
    int v = (t < 256 && i < N_NODES) ? g_deg[i] : 0;
    s[t] = v;
    __syncthreads();
    for (int d = 1; d < 512; d <<= 1) {
        int tmp = (t >= d) ? s[t - d] : 0;
        __syncthreads();
        s[t] += tmp;
        __syncthreads();
    }
    if (t < 256 && i < N_NODES) {
        int off = bpre + s[t] - v;
        g_off[i] = off;
        g_pos[i] = off;
    }
}

__global__ void fill_kernel(const void* __restrict__ ei,
                            const float* __restrict__ ew) {
    int q = blockIdx.x * blockDim.x + threadIdx.x;
    if (q >= N_EDGES / 4) return;
    int mode64 = g_idx64;
    int s0, s1, s2, s3, d0, d1, d2, d3;
    load_idx4(ei, q, 0, mode64, s0, s1, s2, s3);
    load_idx4(ei, q, 1, mode64, d0, d1, d2, d3);
    float4 w = __ldg(reinterpret_cast<const float4*>(ew) + q);
    if ((unsigned)s0 < N_NODES && (unsigned)d0 < N_NODES) {
        int p = atomicAdd(&g_pos[d0], 1);
        g_edge[p] = make_int2(s0, __float_as_int(w.x));
    }
    if ((unsigned)s1 < N_NODES && (unsigned)d1 < N_NODES) {
        int p = atomicAdd(&g_pos[d1], 1);
        g_edge[p] = make_int2(s1, __float_as_int(w.y));
    }
    if ((unsigned)s2 < N_NODES && (unsigned)d2 < N_NODES) {
        int p = atomicAdd(&g_pos[d2], 1);
        g_edge[p] = make_int2(s2, __float_as_int(w.z));
    }
    if ((unsigned)s3 < N_NODES && (unsigned)d3 < N_NODES) {
        int p = atomicAdd(&g_pos[d3], 1);
        g_edge[p] = make_int2(s3, __float_as_int(w.w));
    }
}

// ---------------- gather1: agg1[n] = mean over in-edges of x[src]*w ----------------
__global__ void gather1_kernel(const float* __restrict__ x) {
    int n = (blockIdx.x * blockDim.x + threadIdx.x) >> 5;
    if (n >= N_NODES) return;
    int lane = threadIdx.x & 31;
    int off = g_off[n], end = g_off[n + 1];
    float4 a0 = make_float4(0.f, 0.f, 0.f, 0.f);
    float4 a1 = a0, a2 = a0, a3 = a0;
    int i = off;
    int2 e0, e1, e2, e3;
    bool have = (i + 4 <= end);
    if (have) {
        e0 = __ldg(reinterpret_cast<const int2*>(g_edge) + i + 0);
        e1 = __ldg(reinterpret_cast<const int2*>(g_edge) + i + 1);
        e2 = __ldg(reinterpret_cast<const int2*>(g_edge) + i + 2);
        e3 = __ldg(reinterpret_cast<const int2*>(g_edge) + i + 3);
    }
    for (; i + 8 <= end; i += 4) {
        int2 f0 = __ldg(reinterpret_cast<const int2*>(g_edge) + i + 4);
        int2 f1 = __ldg(reinterpret_cast<const int2*>(g_edge) + i + 5);
        int2 f2 = __ldg(reinterpret_cast<const int2*>(g_edge) + i + 6);
        int2 f3 = __ldg(reinterpret_cast<const int2*>(g_edge) + i + 7);
        float4 v0 = __ldg(reinterpret_cast<const float4*>(x + (size_t)e0.x * D_IN) + lane);
        float4 v1 = __ldg(reinterpret_cast<const float4*>(x + (size_t)e1.x * D_IN) + lane);
        float4 v2 = __ldg(reinterpret_cast<const float4*>(x + (size_t)e2.x * D_IN) + lane);
        float4 v3 = __ldg(reinterpret_cast<const float4*>(x + (size_t)e3.x * D_IN) + lane);
        float w0 = __int_as_float(e0.y), w1 = __int_as_float(e1.y);
        float w2 = __int_as_float(e2.y), w3 = __int_as_float(e3.y);
        a0.x = fmaf(v0.x, w0, a0.x); a0.y = fmaf(v0.y, w0, a0.y);
        a0.z = fmaf(v0.z, w0, a0.z); a0.w = fmaf(v0.w, w0, a0.w);
        a1.x = fmaf(v1.x, w1, a1.x); a1.y = fmaf(v1.y, w1, a1.y);
        a1.z = fmaf(v1.z, w1, a1.z); a1.w = fmaf(v1.w, w1, a1.w);
        a2.x = fmaf(v2.x, w2, a2.x); a2.y = fmaf(v2.y, w2, a2.y);
        a2.z = fmaf(v2.z, w2, a2.z); a2.w = fmaf(v2.w, w2, a2.w);
        a3.x = fmaf(v3.x, w3, a3.x); a3.y = fmaf(v3.y, w3, a3.y);
        a3.z = fmaf(v3.z, w3, a3.z); a3.w = fmaf(v3.w, w3, a3.w);
        e0 = f0; e1 = f1; e2 = f2; e3 = f3;
    }
    if (have) {
        float4 v0 = __ldg(reinterpret_cast<const float4*>(x + (size_t)e0.x * D_IN) + lane);
        float4 v1 = __ldg(reinterpret_cast<const float4*>(x + (size_t)e1.x * D_IN) + lane);
        float4 v2 = __ldg(reinterpret_cast<const float4*>(x + (size_t)e2.x * D_IN) + lane);
        float4 v3 = __ldg(reinterpret_cast<const float4*>(x + (size_t)e3.x * D_IN) + lane);
        float w0 = __int_as_float(e0.y), w1 = __int_as_float(e1.y);
        float w2 = __int_as_float(e2.y), w3 = __int_as_float(e3.y);
        a0.x = fmaf(v0.x, w0, a0.x); a0.y = fmaf(v0.y, w0, a0.y);
        a0.z = fmaf(v0.z, w0, a0.z); a0.w = fmaf(v0.w, w0, a0.w);
        a1.x = fmaf(v1.x, w1, a1.x); a1.y = fmaf(v1.y, w1, a1.y);
        a1.z = fmaf(v1.z, w1, a1.z); a1.w = fmaf(v1.w, w1, a1.w);
        a2.x = fmaf(v2.x, w2, a2.x); a2.y = fmaf(v2.y, w2, a2.y);
        a2.z = fmaf(v2.z, w2, a2.z); a2.w = fmaf(v2.w, w2, a2.w);
        a3.x = fmaf(v3.x, w3, a3.x); a3.y = fmaf(v3.y, w3, a3.y);
        a3.z = fmaf(v3.z, w3, a3.z); a3.w = fmaf(v3.w, w3, a3.w);
        i += 4;
    }
    for (; i < end; ++i) {
        int2 e = __ldg(reinterpret_cast<const int2*>(g_edge) + i);
        float w = __int_as_float(e.y);
        float4 v = __ldg(reinterpret_cast<const float4*>(x + (size_t)e.x * D_IN) + lane);
        a0.x = fmaf(v.x, w, a0.x); a0.y = fmaf(v.y, w, a0.y);
        a0.z = fmaf(v.z, w, a0.z); a0.w = fmaf(v.w, w, a0.w);
    }
    a0.x += (a1.x + a2.x) + a3.x;
    a0.y += (a1.y + a2.y) + a3.y;
    a0.z += (a1.z + a2.z) + a3.z;
    a0.w += (a1.w + a2.w) + a3.w;
    float inv = 1.0f / fmaxf((float)(end - off), 1.0f);
    a0.x *= inv; a0.y *= inv; a0.z *= inv; a0.w *= inv;
    reinterpret_cast<float4*>(g_agg1 + (size_t)n * D_IN)[lane] = a0;
}

// ---------------- layer 1 (tensor-core tf32 mma): h = relu([agg1|x] @ [Wl|Wr]^T + b) ----
#define LTC_WFLOATS (16 * 32 * 32 * 2)     // 32768 floats = 128 KB
#define LTC_FFLOATS (4 * 32 * 32 * 4)      // 16384 floats = 64 KB
#define LTC_SMEM_BYTES ((LTC_WFLOATS + LTC_FFLOATS) * 4)   // 196608
__global__ void layer1_tc_kernel(const float* __restrict__ x,
                                 const float* __restrict__ Wl,
                                 const float* __restrict__ bl,
                                 const float* __restrict__ Wr,
                                 float* __restrict__ hout) {
    extern __shared__ float sm[];
    float* Wf = sm;                    // fragment-order weights
    float* Ff = sm + LTC_WFLOATS;      // fragment-order features
    int t = threadIdx.x;

    for (int it = t; it < 128 * 64; it += 512) {
        int j = it >> 6, k4 = it & 63;
        int k0 = k4 * 4;
        float4 v = (k0 < 128)
            ? __ldg(reinterpret_cast<const float4*>(Wl + (size_t)j * 128 + k0))
            : __ldg(reinterpret_cast<const float4*>(Wr + (size_t)j * 128 + (k0 - 128)));
        int n_tile = j >> 3, g = j & 7;
        int ks = k0 >> 3, slot = (k0 & 7) >> 2;
        float* dst = Wf + ((n_tile * 32 + ks) * 32) * 2 + slot;
        int Lb = g * 4;
        dst[(Lb + 0) * 2] = tf32r(v.x);
        dst[(Lb + 1) * 2] = tf32r(v.y);
        dst[(Lb + 2) * 2] = tf32r(v.z);
        dst[(Lb + 3) * 2] = tf32r(v.w);
    }
    int warp = t >> 5, L = t & 31;
    int mw = warp >> 2, nw = warp & 3;
    int g = L >> 2, tg = L & 3;
    __syncthreads();

    const int NT = (N_NODES + 63) / 64;      // 1563
    for (int tile = blockIdx.x; tile < NT; tile += gridDim.x) {
        int base = tile * 64;
        __syncthreads();
        for (int it = t; it < 64 * 64; it += 512) {
            int nn = it >> 6, k4 = it & 63;
            int node = base + nn; if (node >= N_NODES) node = N_NODES - 1;
            int k0 = k4 * 4;
            float4 v = (k0 < 128)
                ? *reinterpret_cast<const float4*>(g_agg1 + (size_t)node * 128 + k0)
                : __ldg(reinterpret_cast<const float4*>(x + (size_t)node * 128 + (k0 - 128)));
            int m_tile = nn >> 4, r = nn & 15;
            int gg = r & 7, rowhi = r >> 3;
            int ks = k0 >> 3, colhi = (k0 & 7) >> 2;
            int f = rowhi + 2 * colhi;
            float* dst = Ff + ((m_tile * 32 + ks) * 32) * 4 + f;
            int Lb = gg * 4;
            dst[(Lb + 0) * 4] = tf32r(v.x);
            dst[(Lb + 1) * 4] = tf32r(v.y);
            dst[(Lb + 2) * 4] = tf32r(v.z);
            dst[(Lb + 3) * 4] = tf32r(v.w);
        }
        __syncthreads();
        float c[4][4];
        #pragma unroll
        for (int nt = 0; nt < 4; ++nt)
            c[nt][0] = c[nt][1] = c[nt][2] = c[nt][3] = 0.f;
        const float* fa = Ff + (mw * 32) * 128 + L * 4;
        #pragma unroll 4
        for (int ks = 0; ks < 32; ++ks) {
            float4 av = *reinterpret_cast<const float4*>(fa + ks * 128);
            unsigned a0 = __float_as_uint(av.x), a1 = __float_as_uint(av.y);
            unsigned a2 = __float_as_uint(av.z), a3 = __float_as_uint(av.w);
            #pragma unroll
            for (int nt = 0; nt < 4; ++nt) {
                const float* fb = Wf + ((nw * 4 + nt) * 32 + ks) * 64 + L * 2;
                float2 bv = *reinterpret_cast<const float2*>(fb);
                mma_tf32(c[nt][0], c[nt][1], c[nt][2], c[nt][3],
                         a0, a1, a2, a3,
                         __float_as_uint(bv.x), __float_as_uint(bv.y));
            }
        }
        int n0 = base + mw * 16 + g;
        int n1 = n0 + 8;
        #pragma unroll
        for (int nt = 0; nt < 4; ++nt) {
            int j0 = nw * 32 + nt * 8 + tg * 2;
            float b0 = __ldg(&bl[j0]), b1 = __ldg(&bl[j0 + 1]);
            if (n0 < N_NODES) {
                float2 o = make_float2(fmaxf(c[nt][0] + b0, 0.f),
                                       fmaxf(c[nt][1] + b1, 0.f));
                *reinterpret_cast<float2*>(&hout[(size_t)n0 * 128 + j0]) = o;
            }
            if (n1 < N_NODES) {
                float2 o = make_float2(fmaxf(c[nt][2] + b0, 0.f),
                                       fmaxf(c[nt][3] + b1, 0.f));
                *reinterpret_cast<float2*>(&hout[(size_t)n1 * 128 + j0]) = o;
            }
        }
    }
}

// ---------------- tmat2 (tensor-core tf32 mma, fused): [t|r] = h @ [Wl2|Wr2]^T -------
// Same template as layer1_tc with K=128 (16 k-steps); output channel j<64 -> t[j],
// j>=64 -> r[j-64] + b2. 64-node tiles x 128 output channels.
#define T2C_WFLOATS (16 * 16 * 32 * 2)     // 16384 floats = 64 KB
#define T2C_FFLOATS (4 * 16 * 32 * 4)      // 8192 floats = 32 KB
#define T2C_SMEM_BYTES ((T2C_WFLOATS + T2C_FFLOATS) * 4)   // 98304
__global__ void tmat2_tc_kernel(const float* __restrict__ h,
                                const float* __restrict__ Wl2,
                                const float* __restrict__ Wr2,
                                const float* __restrict__ b2) {
    extern __shared__ float sm[];
    float* Wf = sm;
    float* Ff = sm + T2C_WFLOATS;
    int t = threadIdx.x;

    // stage weights: (j 0..127) x (k4 0..31)
    for (int it = t; it < 128 * 32; it += 512) {
        int j = it >> 5, k4 = it & 31;
        int k0 = k4 * 4;
        float4 v = (j < 64)
            ? __ldg(reinterpret_cast<const float4*>(Wl2 + (size_t)j * 128 + k0))
            : __ldg(reinterpret_cast<const float4*>(Wr2 + (size_t)(j - 64) * 128 + k0));
        int n_tile = j >> 3, g = j & 7;
        int ks = k0 >> 3, slot = (k0 & 7) >> 2;
        float* dst = Wf + ((n_tile * 16 + ks) * 32) * 2 + slot;
        int Lb = g * 4;
        dst[(Lb + 0) * 2] = tf32r(v.x);
        dst[(Lb + 1) * 2] = tf32r(v.y);
        dst[(Lb + 2) * 2] = tf32r(v.z);
        dst[(Lb + 3) * 2] = tf32r(v.w);
    }
    int warp = t >> 5, L = t & 31;
    int mw = warp >> 2, nw = warp & 3;
    int g = L >> 2, tg = L & 3;
    __syncthreads();

    const int NT = (N_NODES + 63) / 64;      // 1563
    for (int tile = blockIdx.x; tile < NT; tile += gridDim.x) {
        int base = tile * 64;
        __syncthreads();
        // stage features: (nn 0..63) x (k4 0..31) from h
        for (int it = t; it < 64 * 32; it += 512) {
            int nn = it >> 5, k4 = it & 31;
            int node = base + nn; if (node >= N_NODES) node = N_NODES - 1;
            int k0 = k4 * 4;
            float4 v = *reinterpret_cast<const float4*>(h + (size_t)node * 128 + k0);
            int m_tile = nn >> 4, r = nn & 15;
            int gg = r & 7, rowhi = r >> 3;
            int ks = k0 >> 3, colhi = (k0 & 7) >> 2;
            int f = rowhi + 2 * colhi;
            float* dst = Ff + ((m_tile * 16 + ks) * 32) * 4 + f;
            int Lb = gg * 4;
            dst[(Lb + 0) * 4] = tf32r(v.x);
            dst[(Lb + 1) * 4] = tf32r(v.y);
            dst[(Lb + 2) * 4] = tf32r(v.z);
            dst[(Lb + 3) * 4] = tf32r(v.w);
        }
        __syncthreads();
        float c[4][4];
        #pragma unroll
        for (int nt = 0; nt < 4; ++nt)
            c[nt][0] = c[nt][1] = c[nt][2] = c[nt][3] = 0.f;
        const float* fa = Ff + (mw * 16) * 128 + L * 4;
        #pragma unroll 4
        for (int ks = 0; ks < 16; ++ks) {
            float4 av = *reinterpret_cast<const float4*>(fa + ks * 128);
            unsigned a0 = __float_as_uint(av.x), a1 = __float_as_uint(av.y);
            unsigned a2 = __float_as_uint(av.z), a3 = __float_as_uint(av.w);
            #pragma unroll
            for (int nt = 0; nt < 4; ++nt) {
                const float* fb = Wf + ((nw * 4 + nt) * 16 + ks) * 64 + L * 2;
                float2 bv = *reinterpret_cast<const float2*>(fb);
                mma_tf32(c[nt][0], c[nt][1], c[nt][2], c[nt][3],
                         a0, a1, a2, a3,
                         __float_as_uint(bv.x), __float_as_uint(bv.y));
            }
        }
        int n0 = base + mw * 16 + g;
        int n1 = n0 + 8;
        #pragma unroll
        for (int nt = 0; nt < 4; ++nt) {
            int j0 = nw * 32 + nt * 8 + tg * 2;     // 0..127
            if (j0 < 64) {
                // -> g_t (no bias)
                if (n0 < N_NODES)
                    *reinterpret_cast<float2*>(&g_t[(size_t)n0 * 64 + j0]) =
                        make_float2(c[nt][0], c[nt][1]);
                if (n1 < N_NODES)
                    *reinterpret_cast<float2*>(&g_t[(size_t)n1 * 64 + j0]) =
                        make_float2(c[nt][2], c[nt][3]);
            } else {
                int jr = j0 - 64;
                float b0 = __ldg(&b2[jr]), b1 = __ldg(&b2[jr + 1]);
                if (n0 < N_NODES)
                    *reinterpret_cast<float2*>(&g_r[(size_t)n0 * 64 + jr]) =
                        make_float2(c[nt][0] + b0, c[nt][1] + b1);
                if (n1 < N_NODES)
                    *reinterpret_cast<float2*>(&g_r[(size_t)n1 * 64 + jr]) =
                        make_float2(c[nt][2] + b0, c[nt][3] + b1);
            }
        }
    }
}

// ---------------- gather2 + epilogue: out = mean-agg(t) + r ----------------
__global__ void gather2_kernel(float* __restrict__ out) {
    int gt = blockIdx.x * blockDim.x + threadIdx.x;
    int n = gt >> 4;
    if (n >= N_NODES) return;
    int sub = gt & 15;
    int off = g_off[n], end = g_off[n + 1];
    float4 rv = __ldg(reinterpret_cast<const float4*>(g_r + (size_t)n * D_OUT) + sub);
    float4 a0 = make_float4(0.f, 0.f, 0.f, 0.f);
    float4 a1 = a0, a2 = a0, a3 = a0;
    int i = off;
    int2 e0, e1, e2, e3;
    bool have = (i + 4 <= end);
    if (have) {
        e0 = __ldg(reinterpret_cast<const int2*>(g_edge) + i + 0);
        e1 = __ldg(reinterpret_cast<const int2*>(g_edge) + i + 1);
        e2 = __ldg(reinterpret_cast<const int2*>(g_edge) + i + 2);
        e3 = __ldg(reinterpret_cast<const int2*>(g_edge) + i + 3);
    }
    for (; i + 8 <= end; i += 4) {
        int2 f0 = __ldg(reinterpret_cast<const int2*>(g_edge) + i + 4);
        int2 f1 = __ldg(reinterpret_cast<const int2*>(g_edge) + i + 5);
        int2 f2 = __ldg(reinterpret_cast<const int2*>(g_edge) + i + 6);
        int2 f3 = __ldg(reinterpret_cast<const int2*>(g_edge) + i + 7);
        float4 v0 = __ldg(reinterpret_cast<const float4*>(g_t + (size_t)e0.x * D_OUT) + sub);
        float4 v1 = __ldg(reinterpret_cast<const float4*>(g_t + (size_t)e1.x * D_OUT) + sub);
        float4 v2 = __ldg(reinterpret_cast<const float4*>(g_t + (size_t)e2.x * D_OUT) + sub);
        float4 v3 = __ldg(reinterpret_cast<const float4*>(g_t + (size_t)e3.x * D_OUT) + sub);
        float w0 = __int_as_float(e0.y), w1 = __int_as_float(e1.y);
        float w2 = __int_as_float(e2.y), w3 = __int_as_float(e3.y);
        a0.x = fmaf(v0.x, w0, a0.x); a0.y = fmaf(v0.y, w0, a0.y);
        a0.z = fmaf(v0.z, w0, a0.z); a0.w = fmaf(v0.w, w0, a0.w);
        a1.x = fmaf(v1.x, w1, a1.x); a1.y = fmaf(v1.y, w1, a1.y);
        a1.z = fmaf(v1.z, w1, a1.z); a1.w = fmaf(v1.w, w1, a1.w);
        a2.x = fmaf(v2.x, w2, a2.x); a2.y = fmaf(v2.y, w2, a2.y);
        a2.z = fmaf(v2.z, w2, a2.z); a2.w = fmaf(v2.w, w2, a2.w);
        a3.x = fmaf(v3.x, w3, a3.x); a3.y = fmaf(v3.y, w3, a3.y);
        a3.z = fmaf(v3.z, w3, a3.z); a3.w = fmaf(v3.w, w3, a3.w);
        e0 = f0; e1 = f1; e2 = f2; e3 = f3;
    }
    if (have) {
        float4 v0 = __ldg(reinterpret_cast<const float4*>(g_t + (size_t)e0.x * D_OUT) + sub);
        float4 v1 = __ldg(reinterpret_cast<const float4*>(g_t + (size_t)e1.x * D_OUT) + sub);
        float4 v2 = __ldg(reinterpret_cast<const float4*>(g_t + (size_t)e2.x * D_OUT) + sub);
        float4 v3 = __ldg(reinterpret_cast<const float4*>(g_t + (size_t)e3.x * D_OUT) + sub);
        float w0 = __int_as_float(e0.y), w1 = __int_as_float(e1.y);
        float w2 = __int_as_float(e2.y), w3 = __int_as_float(e3.y);
        a0.x = fmaf(v0.x, w0, a0.x); a0.y = fmaf(v0.y, w0, a0.y);
        a0.z = fmaf(v0.z, w0, a0.z); a0.w = fmaf(v0.w, w0, a0.w);
        a1.x = fmaf(v1.x, w1, a1.x); a1.y = fmaf(v1.y, w1, a1.y);
        a1.z = fmaf(v1.z, w1, a1.z); a1.w = fmaf(v1.w, w1, a1.w);
        a2.x = fmaf(v2.x, w2, a2.x); a2.y = fmaf(v2.y, w2, a2.y);
        a2.z = fmaf(v2.z, w2, a2.z); a2.w = fmaf(v2.w, w2, a2.w);
        a3.x = fmaf(v3.x, w3, a3.x); a3.y = fmaf(v3.y, w3, a3.y);
        a3.z = fmaf(v3.z, w3, a3.z); a3.w = fmaf(v3.w, w3, a3.w);
        i += 4;
    }
    for (; i < end; ++i) {
        int2 e = __ldg(reinterpret_cast<const int2*>(g_edge) + i);
        float w = __int_as_float(e.y);
        float4 v = __ldg(reinterpret_cast<const float4*>(g_t + (size_t)e.x * D_OUT) + sub);
        a0.x = fmaf(v.x, w, a0.x); a0.y = fmaf(v.y, w, a0.y);
        a0.z = fmaf(v.z, w, a0.z); a0.w = fmaf(v.w, w, a0.w);
    }
    a0.x += (a1.x + a2.x) + a3.x;
    a0.y += (a1.y + a2.y) + a3.y;
    a0.z += (a1.z + a2.z) + a3.z;
    a0.w += (a1.w + a2.w) + a3.w;
    float inv = 1.0f / fmaxf((float)(end - off), 1.0f);
    a0.x = fmaf(a0.x, inv, rv.x);
    a0.y = fmaf(a0.y, inv, rv.y);
    a0.z = fmaf(a0.z, inv, rv.z);
    a0.w = fmaf(a0.w, inv, rv.w);
    reinterpret_cast<float4*>(out + (size_t)n * D_OUT)[sub] = a0;
}

// ---------------- launch ----------------
extern "C" void kernel_launch(void* const* d_in, const int* in_sizes, int n_in,
                              void* d_out, int out_size) {
    (void)in_sizes; (void)n_in;
    const float* x   = (const float*)d_in[0];
    const void*  ei  = d_in[1];                 // int32 or int64, detected on device
    const float* ew  = (const float*)d_in[2];
    const float* Wl1 = (const float*)d_in[3];
    const float* bl1 = (const float*)d_in[4];
    const float* Wr1 = (const float*)d_in[5];
    const float* Wl2 = (const float*)d_in[6];
    const float* bl2 = (const float*)d_in[7];
    const float* Wr2 = (const float*)d_in[8];

    float* hptr;
    float* lptr;
    const size_t full = (size_t)N_NODES * (D_HID + D_OUT);
    if ((size_t)out_size >= full) {
        hptr = (float*)d_out;
        lptr = hptr + (size_t)N_NODES * D_HID;
    } else {
        void* sym = nullptr;
        cudaGetSymbolAddress(&sym, g_h);
        hptr = (float*)sym;
        lptr = (float*)d_out;
    }

    int smcount = 148;
    if (cudaDeviceGetAttribute(&smcount, cudaDevAttrMultiProcessorCount, 0) != cudaSuccess)
        smcount = 148;

    cudaFuncSetAttribute(layer1_tc_kernel,
                         cudaFuncAttributeMaxDynamicSharedMemorySize, LTC_SMEM_BYTES);
    cudaFuncSetAttribute(tmat2_tc_kernel,
                         cudaFuncAttributeMaxDynamicSharedMemorySize, T2C_SMEM_BYTES);

    detect_zero_kernel<<<NBLK, 256>>>((const int*)ei);       // 1
    hist_kernel<<<N_EDGES / 4 / 256, 256>>>(ei);             // 2
    blocksum_kernel<<<NBLK, 256>>>();                        // 3
    offsets_kernel<<<NBLK, 512>>>();                         // 4
    fill_kernel<<<N_EDGES / 4 / 256, 256>>>(ei, ew);         // 5
    gather1_kernel<<<(N_NODES * 32 + 255) / 256, 256>>>(x);  // 6
    layer1_tc_kernel<<<smcount, 512, LTC_SMEM_BYTES>>>(x, Wl1, bl1, Wr1, hptr);
    tmat2_tc_kernel<<<smcount, 512, T2C_SMEM_BYTES>>>(hptr, Wl2, Wr2, bl2);
    gather2_kernel<<<(N_NODES * 16 + 255) / 256, 256>>>(lptr);
}